// round 14
// baseline (speedup 1.0000x reference)
#include <cuda_runtime.h>
#include <cuda_fp16.h>
#include <cstdint>

// Problem constants
#define Bb  4
#define Tt  2048
#define Dd  1024
#define Hh  16
#define HDh 64
#define Mm  (Bb * Tt)   // 8192 rows

// ---------------------------------------------------------------------------
// Scratch (device globals: allocation-free rule). All fp16.
// ---------------------------------------------------------------------------
__device__ __half g_xh[(size_t)Mm * Dd];
__device__ __half g_xl[(size_t)Mm * Dd];
__device__ __half g_qh[(size_t)Mm * Dd];
__device__ __half g_ql[(size_t)Mm * Dd];
__device__ __half g_kh[(size_t)Mm * Dd];          // K single-rounded
__device__ __half g_vh[(size_t)Mm * Dd];          // V single-rounded
__device__ __half g_ch[(size_t)Mm * Dd];
__device__ __half g_cl[(size_t)Mm * Dd];
__device__ __half g_wh[4 * (size_t)Dd * Dd];
__device__ __half g_wl[4 * (size_t)Dd * Dd];

// ---------------------------------------------------------------------------
// sm_100-base helpers: cp.async + mma.sync fp16 (tcgen05 unavailable here)
// ---------------------------------------------------------------------------
__device__ __forceinline__ uint32_t smem_to_u32(const void* p) {
    uint32_t a;
    asm("{ .reg .u64 t; cvta.to.shared.u64 t, %1; cvt.u32.u64 %0, t; }"
        : "=r"(a) : "l"(p));
    return a;
}
__device__ __forceinline__ void cp_async16(uint32_t smem_addr, const void* gptr) {
    asm volatile("cp.async.cg.shared.global [%0], [%1], 16;"
                 :: "r"(smem_addr), "l"(gptr));
}
__device__ __forceinline__ void cp_commit() {
    asm volatile("cp.async.commit_group;");
}
template <int N>
__device__ __forceinline__ void cp_wait() {
    asm volatile("cp.async.wait_group %0;" :: "n"(N));
}
// D += A*B, m16n8k16 fp16 in / fp32 accum; A row-major, B col-major
__device__ __forceinline__ void mma16816(float* d, const uint32_t* a, const uint32_t* b) {
    asm volatile(
        "mma.sync.aligned.m16n8k16.row.col.f32.f16.f16.f32 "
        "{%0,%1,%2,%3}, {%4,%5,%6,%7}, {%8,%9}, {%0,%1,%2,%3};"
        : "+f"(d[0]), "+f"(d[1]), "+f"(d[2]), "+f"(d[3])
        : "r"(a[0]), "r"(a[1]), "r"(a[2]), "r"(a[3]), "r"(b[0]), "r"(b[1]));
}
__device__ __forceinline__ uint32_t h2_bits(__half2 v) {
    union { __half2 h; uint32_t u; } cv; cv.h = v; return cv.u;
}
// hi/lo split of one float into two fp16
__device__ __forceinline__ void split_h(float v, __half& hi, __half& lo) {
    hi = __float2half_rn(v);
    lo = __float2half_rn(v - __half2float(hi));
}

// ---------------------------------------------------------------------------
// Split kernels (fp32 -> fp16 hi/lo)
// ---------------------------------------------------------------------------
__global__ __launch_bounds__(256) void split_x_kernel(
    const float* __restrict__ src,
    __half* __restrict__ hi, __half* __restrict__ lo, int n4)
{
    int i = blockIdx.x * blockDim.x + threadIdx.x;
    if (i >= n4) return;
    float4 v = ((const float4*)src)[i];
    __half h0, h1, h2, h3, l0, l1, l2, l3;
    split_h(v.x, h0, l0); split_h(v.y, h1, l1);
    split_h(v.z, h2, l2); split_h(v.w, h3, l3);
    union { __half b[4]; uint2 u; } ph, pl;
    ph.b[0] = h0; ph.b[1] = h1; ph.b[2] = h2; ph.b[3] = h3;
    pl.b[0] = l0; pl.b[1] = l1; pl.b[2] = l2; pl.b[3] = l3;
    ((uint2*)hi)[i] = ph.u;
    ((uint2*)lo)[i] = pl.u;
}

// all 4 weight matrices in one launch; dest arrays are contiguous per-matrix
__global__ __launch_bounds__(256) void split_w4_kernel(
    const float* __restrict__ w0, const float* __restrict__ w1,
    const float* __restrict__ w2, const float* __restrict__ w3,
    __half* __restrict__ hi, __half* __restrict__ lo, int n4_each)
{
    int i = blockIdx.x * blockDim.x + threadIdx.x;
    if (i >= 4 * n4_each) return;
    const int m = i / n4_each, j = i - m * n4_each;
    const float* src = (m == 0) ? w0 : (m == 1) ? w1 : (m == 2) ? w2 : w3;
    float4 v = ((const float4*)src)[j];
    __half h0, h1, h2, h3, l0, l1, l2, l3;
    split_h(v.x, h0, l0); split_h(v.y, h1, l1);
    split_h(v.z, h2, l2); split_h(v.w, h3, l3);
    union { __half b[4]; uint2 u; } ph, pl;
    ph.b[0] = h0; ph.b[1] = h1; ph.b[2] = h2; ph.b[3] = h3;
    pl.b[0] = l0; pl.b[1] = l1; pl.b[2] = l2; pl.b[3] = l3;
    ((uint2*)hi)[i] = ph.u;
    ((uint2*)lo)[i] = pl.u;
}

// ---------------------------------------------------------------------------
// 3-pass fp16 split GEMM (Q projection): C = (Ah+Al) @ (Bh+Bl)^T + bias,
// dropping Al*Bl. BK=32, double-buffered, single sync per chunk.
// Output: fp16 hi/lo, scaled.
// ---------------------------------------------------------------------------
#define GPITCH 40
#define GTILE_B (128 * GPITCH * 2)
#define GSTAGE_B (4 * GTILE_B)
#define GSMEM_B (2 * GSTAGE_B)

__global__ __launch_bounds__(256, 2) void gemm3p_bk32(
    const __half* __restrict__ Ah, const __half* __restrict__ Al,
    const __half* __restrict__ Bh, const __half* __restrict__ Bl,
    const float* __restrict__ bias,
    __half* __restrict__ Oh, __half* __restrict__ Ol, float scale)
{
    extern __shared__ __align__(128) uint8_t smem[];
    const int tid  = threadIdx.x;
    const int wid  = tid >> 5;
    const int lane = tid & 31;
    const int wm   = wid & 3;
    const int wn   = wid >> 2;
    const int gm0  = blockIdx.y * 128;
    const int gn0  = blockIdx.x * 128;
    const uint32_t sbase = smem_to_u32(smem);

    const __half* srcs[4] = { Ah, Al, Bh, Bl };

    auto issue = [&](int s, int c) {
        const int k0 = c * 32;
#pragma unroll
        for (int t = 0; t < 4; ++t) {
            const __half* src = srcs[t];
            const int rbase = (t < 2) ? gm0 : gn0;
#pragma unroll
            for (int j = 0; j < 2; ++j) {
                const int i = tid + j * 256;
                const int row = i >> 2, chunk = i & 3;
                const uint32_t sa = sbase + s * GSTAGE_B + t * GTILE_B
                                  + (uint32_t)(row * GPITCH + chunk * 8) * 2;
                const void* g = src + (size_t)(rbase + row) * Dd + k0 + chunk * 8;
                cp_async16(sa, g);
            }
        }
        cp_commit();
    };

    float acc[2][8][4];
#pragma unroll
    for (int mt = 0; mt < 2; ++mt)
#pragma unroll
        for (int nt = 0; nt < 8; ++nt)
#pragma unroll
            for (int q = 0; q < 4; ++q) acc[mt][nt][q] = 0.f;

    const int r   = lane >> 2;
    const int cp2 = (lane & 3) * 2;

    issue(0, 0);

    for (int c = 0; c < 32; ++c) {
        const int s = c & 1;
        cp_wait<0>();
        __syncthreads();
        if (c + 1 < 32) issue(s ^ 1, c + 1);

        const uint8_t* stg = smem + s * GSTAGE_B;
        const uint8_t* pAh = stg;
        const uint8_t* pAl = stg + GTILE_B;
        const uint8_t* pBh = stg + 2 * GTILE_B;
        const uint8_t* pBl = stg + 3 * GTILE_B;

#pragma unroll
        for (int ks = 0; ks < 2; ++ks) {
            const int kk = ks * 16;
            uint32_t ah[2][4], al[2][4];
#pragma unroll
            for (int mt = 0; mt < 2; ++mt) {
                const int row = wm * 32 + mt * 16 + r;
                const uint32_t o00 = (uint32_t)(row * GPITCH + kk + cp2) * 2;
                const uint32_t o10 = (uint32_t)((row + 8) * GPITCH + kk + cp2) * 2;
                ah[mt][0] = *(const uint32_t*)(pAh + o00);
                ah[mt][1] = *(const uint32_t*)(pAh + o10);
                ah[mt][2] = *(const uint32_t*)(pAh + o00 + 16);
                ah[mt][3] = *(const uint32_t*)(pAh + o10 + 16);
                al[mt][0] = *(const uint32_t*)(pAl + o00);
                al[mt][1] = *(const uint32_t*)(pAl + o10);
                al[mt][2] = *(const uint32_t*)(pAl + o00 + 16);
                al[mt][3] = *(const uint32_t*)(pAl + o10 + 16);
            }
#pragma unroll
            for (int nh = 0; nh < 2; ++nh) {
                uint32_t bh[4][2], bl[4][2];
#pragma unroll
                for (int nt = 0; nt < 4; ++nt) {
                    const int n = wn * 64 + (nh * 4 + nt) * 8 + r;
                    const uint32_t ob = (uint32_t)(n * GPITCH + kk + cp2) * 2;
                    bh[nt][0] = *(const uint32_t*)(pBh + ob);
                    bh[nt][1] = *(const uint32_t*)(pBh + ob + 16);
                    bl[nt][0] = *(const uint32_t*)(pBl + ob);
                    bl[nt][1] = *(const uint32_t*)(pBl + ob + 16);
                }
#pragma unroll
                for (int nt = 0; nt < 4; ++nt) {
                    mma16816(acc[0][nh * 4 + nt], ah[0], bh[nt]);
                    mma16816(acc[1][nh * 4 + nt], ah[1], bh[nt]);
                }
#pragma unroll
                for (int nt = 0; nt < 4; ++nt) {
                    mma16816(acc[0][nh * 4 + nt], al[0], bh[nt]);
                    mma16816(acc[1][nh * 4 + nt], al[1], bh[nt]);
                }
#pragma unroll
                for (int nt = 0; nt < 4; ++nt) {
                    mma16816(acc[0][nh * 4 + nt], ah[0], bl[nt]);
                    mma16816(acc[1][nh * 4 + nt], ah[1], bl[nt]);
                }
            }
        }
    }

    // Epilogue: scaled fp16 hi/lo
#pragma unroll
    for (int mt = 0; mt < 2; ++mt) {
        const int row0 = gm0 + wm * 32 + mt * 16 + r;
#pragma unroll
        for (int nt = 0; nt < 8; ++nt) {
            const int col = gn0 + wn * 64 + nt * 8 + cp2;
            const float b0 = bias[col], b1 = bias[col + 1];
            float v0 = (acc[mt][nt][0] + b0) * scale, v1 = (acc[mt][nt][1] + b1) * scale;
            float v2 = (acc[mt][nt][2] + b0) * scale, v3 = (acc[mt][nt][3] + b1) * scale;
            __half2 h01 = __floats2half2_rn(v0, v1);
            __half2 h23 = __floats2half2_rn(v2, v3);
            __half2 l01 = __floats2half2_rn(
                v0 - __half2float(__low2half(h01)), v1 - __half2float(__high2half(h01)));
            __half2 l23 = __floats2half2_rn(
                v2 - __half2float(__low2half(h23)), v3 - __half2float(__high2half(h23)));
            *(uint32_t*)(Oh + (size_t)row0 * Dd + col)       = h2_bits(h01);
            *(uint32_t*)(Ol + (size_t)row0 * Dd + col)       = h2_bits(l01);
            *(uint32_t*)(Oh + (size_t)(row0 + 8) * Dd + col) = h2_bits(h23);
            *(uint32_t*)(Ol + (size_t)(row0 + 8) * Dd + col) = h2_bits(l23);
        }
    }
}

// ---------------------------------------------------------------------------
// 2-pass fp16 split GEMM (K/V/O projections): C = (Ah+Al) @ Bh^T + bias.
// BK=64 (3 tiles/stage, 110.6 KB smem, 2 CTAs/SM), single sync per chunk.
// Output: fp16 single (Oh) or fp32 (Cf32).
// ---------------------------------------------------------------------------
#define G2PITCH 72
#define G2TILE_B (128 * G2PITCH * 2)      // 18432
#define G2STAGE_B (3 * G2TILE_B)          // 55296
#define G2SMEM_B (2 * G2STAGE_B)          // 110592

__global__ __launch_bounds__(256, 2) void gemm2p_bk64(
    const __half* __restrict__ Ah, const __half* __restrict__ Al,
    const __half* __restrict__ Bh,
    const float* __restrict__ bias,
    float* __restrict__ Cf32, __half* __restrict__ Oh)
{
    extern __shared__ __align__(128) uint8_t smem[];
    const int tid  = threadIdx.x;
    const int wid  = tid >> 5;
    const int lane = tid & 31;
    const int wm   = wid & 3;
    const int wn   = wid >> 2;
    const int gm0  = blockIdx.y * 128;
    const int gn0  = blockIdx.x * 128;
    const uint32_t sbase = smem_to_u32(smem);

    const __half* srcs[3] = { Ah, Al, Bh };

    auto issue = [&](int s, int c) {
        const int k0 = c * 64;
#pragma unroll
        for (int t = 0; t < 3; ++t) {
            const __half* src = srcs[t];
            const int rbase = (t < 2) ? gm0 : gn0;
#pragma unroll
            for (int j = 0; j < 4; ++j) {
                const int i = tid + j * 256;
                const int row = i >> 3, seg = i & 7;
                const uint32_t sa = sbase + s * G2STAGE_B + t * G2TILE_B
                                  + (uint32_t)(row * G2PITCH + seg * 8) * 2;
                const void* g = src + (size_t)(rbase + row) * Dd + k0 + seg * 8;
                cp_async16(sa, g);
            }
        }
        cp_commit();
    };

    float acc[2][8][4];
#pragma unroll
    for (int mt = 0; mt < 2; ++mt)
#pragma unroll
        for (int nt = 0; nt < 8; ++nt)
#pragma unroll
            for (int q = 0; q < 4; ++q) acc[mt][nt][q] = 0.f;

    const int r   = lane >> 2;
    const int cp2 = (lane & 3) * 2;

    issue(0, 0);

    for (int c = 0; c < 16; ++c) {
        const int s = c & 1;
        cp_wait<0>();
        __syncthreads();
        if (c + 1 < 16) issue(s ^ 1, c + 1);

        const uint8_t* stg = smem + s * G2STAGE_B;
        const uint8_t* pAh = stg;
        const uint8_t* pAl = stg + G2TILE_B;
        const uint8_t* pBh = stg + 2 * G2TILE_B;

#pragma unroll
        for (int ks = 0; ks < 4; ++ks) {
            const int kk = ks * 16;
            uint32_t ah[2][4], al[2][4];
#pragma unroll
            for (int mt = 0; mt < 2; ++mt) {
                const int row = wm * 32 + mt * 16 + r;
                const uint32_t o00 = (uint32_t)(row * G2PITCH + kk + cp2) * 2;
                const uint32_t o10 = (uint32_t)((row + 8) * G2PITCH + kk + cp2) * 2;
                ah[mt][0] = *(const uint32_t*)(pAh + o00);
                ah[mt][1] = *(const uint32_t*)(pAh + o10);
                ah[mt][2] = *(const uint32_t*)(pAh + o00 + 16);
                ah[mt][3] = *(const uint32_t*)(pAh + o10 + 16);
                al[mt][0] = *(const uint32_t*)(pAl + o00);
                al[mt][1] = *(const uint32_t*)(pAl + o10);
                al[mt][2] = *(const uint32_t*)(pAl + o00 + 16);
                al[mt][3] = *(const uint32_t*)(pAl + o10 + 16);
            }
#pragma unroll
            for (int nh = 0; nh < 2; ++nh) {
                uint32_t bh[4][2];
#pragma unroll
                for (int nt = 0; nt < 4; ++nt) {
                    const int n = wn * 64 + (nh * 4 + nt) * 8 + r;
                    const uint32_t ob = (uint32_t)(n * G2PITCH + kk + cp2) * 2;
                    bh[nt][0] = *(const uint32_t*)(pBh + ob);
                    bh[nt][1] = *(const uint32_t*)(pBh + ob + 16);
                }
#pragma unroll
                for (int nt = 0; nt < 4; ++nt) {
                    mma16816(acc[0][nh * 4 + nt], ah[0], bh[nt]);
                    mma16816(acc[1][nh * 4 + nt], ah[1], bh[nt]);
                }
#pragma unroll
                for (int nt = 0; nt < 4; ++nt) {
                    mma16816(acc[0][nh * 4 + nt], al[0], bh[nt]);
                    mma16816(acc[1][nh * 4 + nt], al[1], bh[nt]);
                }
            }
        }
    }

    // Epilogue
#pragma unroll
    for (int mt = 0; mt < 2; ++mt) {
        const int row0 = gm0 + wm * 32 + mt * 16 + r;
#pragma unroll
        for (int nt = 0; nt < 8; ++nt) {
            const int col = gn0 + wn * 64 + nt * 8 + cp2;
            const float b0 = bias[col], b1 = bias[col + 1];
            float v0 = acc[mt][nt][0] + b0, v1 = acc[mt][nt][1] + b1;
            float v2 = acc[mt][nt][2] + b0, v3 = acc[mt][nt][3] + b1;
            if (Cf32) {
                float2 w0, w1;
                w0.x = v0; w0.y = v1; w1.x = v2; w1.y = v3;
                *(float2*)(Cf32 + (size_t)row0 * Dd + col)       = w0;
                *(float2*)(Cf32 + (size_t)(row0 + 8) * Dd + col) = w1;
            } else {
                __half2 h01 = __floats2half2_rn(v0, v1);
                __half2 h23 = __floats2half2_rn(v2, v3);
                *(uint32_t*)(Oh + (size_t)row0 * Dd + col)       = h2_bits(h01);
                *(uint32_t*)(Oh + (size_t)(row0 + 8) * Dd + col) = h2_bits(h23);
            }
        }
    }
}

// ---------------------------------------------------------------------------
// Flash attention, fp16 mma.sync.
// S = (Qh+Ql) @ K (2 MMAs); PV = Ph @ Vh (1 MMA, l exact fp32).
// R14: single __syncthreads per iter — V^T double-buffered (staged for c+1
// during iter c), bias row hoisted to preamble (full 2048 entries, 8 KB).
// Grid (T/128, H, B), 256 threads = 8 warps; warp w owns q rows [16w,16w+16).
// Q pre-scaled by 1/8 in the Q projection epilogue.
// ---------------------------------------------------------------------------
#define QPITCH 72     // fp16; pitch%64==8 -> conflict-free frag loads
#define VPITCH 136
#define VBUF_B  17408
#define AT_QH   0
#define AT_QL   18432
#define AT_K0   36864          // + s*18432 (K hi only)
#define AT_VH   73728          // + (c&1)*VBUF_B  (double-buffered)
#define AT_BIAS 108544         // full 2048-entry f32 bias row
#define AT_SMEM 116736

__global__ __launch_bounds__(256, 1) void attn_mma_kernel(
    const __half* __restrict__ qh, const __half* __restrict__ ql,
    const __half* __restrict__ kh,
    const __half* __restrict__ vh,
    const int* __restrict__ mask,
    __half* __restrict__ och, __half* __restrict__ ocl)
{
    extern __shared__ __align__(128) uint8_t sm[];
    const uint32_t sb = smem_to_u32(sm);
    const int tid = threadIdx.x, wid = tid >> 5, lane = tid & 31;
    const int r = lane >> 2, c2 = (lane & 3) * 2;
    const int b = blockIdx.z, h = blockIdx.y;
    const int q0 = blockIdx.x * 128;
    const size_t gq = ((size_t)(b * Tt + q0)) * Dd + h * HDh;
    const size_t gk = ((size_t)(b * Tt)) * Dd + h * HDh;
    const int* mb = mask + b * Tt;

    // ---- preamble: stage Q (hi/lo) and K tile 0 via cp.async
#pragma unroll
    for (int j = 0; j < 4; ++j) {
        const int i = tid + j * 256, row = i >> 3, seg = i & 7;
        const uint32_t so = (uint32_t)((row * QPITCH + seg * 8) * 2);
        const size_t go = (size_t)row * Dd + seg * 8;
        cp_async16(sb + AT_QH + so, qh + gq + go);
        cp_async16(sb + AT_QL + so, ql + gq + go);
        cp_async16(sb + AT_K0 + so, kh + gk + go);
    }
    cp_commit();

    // ---- full bias row (hoisted; visible after first loop-top sync)
#pragma unroll
    for (int j = 0; j < 8; ++j) {
        const int idx = tid + j * 256;
        ((float*)(sm + AT_BIAS))[idx] = (mb[idx] == 0) ? -1e30f : 0.f;
    }

    // ---- V: load rows for tile 0, stage V^T(0) into buf 0, prefetch tile 1
    const int vj = tid >> 2;
    const int vq = tid & 3;
    uint4 vr_h[2][2];
    auto load_v = [&](int kvbase) {
#pragma unroll
        for (int rr = 0; rr < 2; ++rr) {
            const size_t g = ((size_t)(b * Tt + kvbase + 2 * vj + rr)) * Dd + h * HDh + vq * 16;
            vr_h[rr][0] = *(const uint4*)(vh + g);
            vr_h[rr][1] = *(const uint4*)(vh + g + 8);
        }
    };
    auto stage_vt = [&](int buf) {
        uint8_t* vb = sm + AT_VH + buf * VBUF_B;
#pragma unroll
        for (int w = 0; w < 8; ++w) {
            const uint32_t a0 = ((const uint32_t*)&vr_h[0])[w];
            const uint32_t a1 = ((const uint32_t*)&vr_h[1])[w];
            const int hd = vq * 16 + 2 * w;
            *(uint32_t*)(vb + ((hd)     * VPITCH + 2 * vj) * 2) = __byte_perm(a0, a1, 0x5410);
            *(uint32_t*)(vb + ((hd + 1) * VPITCH + 2 * vj) * 2) = __byte_perm(a0, a1, 0x7632);
        }
    };
    load_v(0);
    stage_vt(0);
    load_v(128);

    float cacc[8][4];
#pragma unroll
    for (int nt = 0; nt < 8; ++nt)
#pragma unroll
        for (int q = 0; q < 4; ++q) cacc[nt][q] = 0.f;
    float m0 = -1e30f, m1 = -1e30f, l0 = 0.f, l1 = 0.f;
    uint32_t qAh[4][4], qAl[4][4];

    for (int c = 0; c < 16; ++c) {
        const int kv0 = c * 128;
        const int s = c & 1;
        cp_wait<0>();
        __syncthreads();   // K(c), V^T(c), bias visible; buf (c+1)&1 reads retired

        if (c == 0) {   // Q A-frags, hoisted
#pragma unroll
            for (int kt = 0; kt < 4; ++kt) {
                const uint32_t o  = (uint32_t)(((wid * 16 + r) * QPITCH + kt * 16 + c2) * 2);
                const uint32_t o8 = o + 8 * QPITCH * 2;
                qAh[kt][0] = *(const uint32_t*)(sm + AT_QH + o);
                qAh[kt][1] = *(const uint32_t*)(sm + AT_QH + o8);
                qAh[kt][2] = *(const uint32_t*)(sm + AT_QH + o + 16);
                qAh[kt][3] = *(const uint32_t*)(sm + AT_QH + o8 + 16);
                qAl[kt][0] = *(const uint32_t*)(sm + AT_QL + o);
                qAl[kt][1] = *(const uint32_t*)(sm + AT_QL + o8);
                qAl[kt][2] = *(const uint32_t*)(sm + AT_QL + o + 16);
                qAl[kt][3] = *(const uint32_t*)(sm + AT_QL + o8 + 16);
            }
        }

        // prefetch K(c+1) -> stage s^1
        if (c + 1 < 16) {
#pragma unroll
            for (int j = 0; j < 4; ++j) {
                const int i = tid + j * 256, row = i >> 3, seg = i & 7;
                const uint32_t so = (uint32_t)((row * QPITCH + seg * 8) * 2);
                const size_t g = gk + (size_t)(kv0 + 128 + row) * Dd + seg * 8;
                cp_async16(sb + AT_K0 + (s ^ 1) * 18432 + so, kh + g);
            }
        }
        cp_commit();

        // stage V^T(c+1) into buf (c+1)&1 (WAR-safe: buf reads retired at sync)
        if (c + 1 < 16) {
            stage_vt((c + 1) & 1);
            if (c + 2 < 16) load_v(kv0 + 256);
        }

        // ---- S = (Qh+Ql) K^T  (pass-ordered, distance-8 acc reuse)
        const uint8_t* Ksh = sm + AT_K0 + s * 18432;
        float sacc[16][4];
#pragma unroll
        for (int nt = 0; nt < 16; ++nt)
#pragma unroll
            for (int q = 0; q < 4; ++q) sacc[nt][q] = 0.f;
#pragma unroll
        for (int kt = 0; kt < 4; ++kt) {
#pragma unroll
            for (int nh = 0; nh < 2; ++nh) {
                uint32_t bk2[8][2];
#pragma unroll
                for (int nt = 0; nt < 8; ++nt) {
                    const uint32_t o = (uint32_t)((((nh * 8 + nt) * 8 + r) * QPITCH + kt * 16 + c2) * 2);
                    bk2[nt][0] = *(const uint32_t*)(Ksh + o);
                    bk2[nt][1] = *(const uint32_t*)(Ksh + o + 16);
                }
#pragma unroll
                for (int nt = 0; nt < 8; ++nt)
                    mma16816(sacc[nh * 8 + nt], qAh[kt], bk2[nt]);
#pragma unroll
                for (int nt = 0; nt < 8; ++nt)
                    mma16816(sacc[nh * 8 + nt], qAl[kt], bk2[nt]);
            }
        }

        // ---- mask bias + online softmax
        const float* bias = (const float*)(sm + AT_BIAS) + kv0;
        float tmax0 = -1e30f, tmax1 = -1e30f;
#pragma unroll
        for (int nt = 0; nt < 16; ++nt) {
            const float2 bv = *(const float2*)(bias + nt * 8 + c2);
            sacc[nt][0] += bv.x; sacc[nt][1] += bv.y;
            sacc[nt][2] += bv.x; sacc[nt][3] += bv.y;
            tmax0 = fmaxf(tmax0, fmaxf(sacc[nt][0], sacc[nt][1]));
            tmax1 = fmaxf(tmax1, fmaxf(sacc[nt][2], sacc[nt][3]));
        }
        tmax0 = fmaxf(tmax0, __shfl_xor_sync(0xffffffffu, tmax0, 1));
        tmax0 = fmaxf(tmax0, __shfl_xor_sync(0xffffffffu, tmax0, 2));
        tmax1 = fmaxf(tmax1, __shfl_xor_sync(0xffffffffu, tmax1, 1));
        tmax1 = fmaxf(tmax1, __shfl_xor_sync(0xffffffffu, tmax1, 2));
        const float mn0 = fmaxf(m0, tmax0), mn1 = fmaxf(m1, tmax1);
        const float al0 = __expf(m0 - mn0), al1 = __expf(m1 - mn1);
        m0 = mn0; m1 = mn1;
        float rs0 = 0.f, rs1 = 0.f;
#pragma unroll
        for (int nt = 0; nt < 16; ++nt) {
            sacc[nt][0] = __expf(sacc[nt][0] - mn0);
            sacc[nt][1] = __expf(sacc[nt][1] - mn0);
            sacc[nt][2] = __expf(sacc[nt][2] - mn1);
            sacc[nt][3] = __expf(sacc[nt][3] - mn1);
            rs0 += sacc[nt][0] + sacc[nt][1];
            rs1 += sacc[nt][2] + sacc[nt][3];
        }
        rs0 += __shfl_xor_sync(0xffffffffu, rs0, 1);
        rs0 += __shfl_xor_sync(0xffffffffu, rs0, 2);
        rs1 += __shfl_xor_sync(0xffffffffu, rs1, 1);
        rs1 += __shfl_xor_sync(0xffffffffu, rs1, 2);
        l0 = l0 * al0 + rs0;
        l1 = l1 * al1 + rs1;
#pragma unroll
        for (int nt = 0; nt < 8; ++nt) {
            cacc[nt][0] *= al0; cacc[nt][1] *= al0;
            cacc[nt][2] *= al1; cacc[nt][3] *= al1;
        }

        // ---- PV: P (single fp16) x V^T(c) from buf c&1
        const uint8_t* Vsh = sm + AT_VH + (c & 1) * VBUF_B;
#pragma unroll
        for (int kt = 0; kt < 8; ++kt) {
            uint32_t aPh[4];
#pragma unroll
            for (int u = 0; u < 2; ++u) {
                const float p0 = sacc[2 * kt + u][0], p1 = sacc[2 * kt + u][1];
                const float p2 = sacc[2 * kt + u][2], p3 = sacc[2 * kt + u][3];
                aPh[2 * u + 0] = h2_bits(__floats2half2_rn(p0, p1));
                aPh[2 * u + 1] = h2_bits(__floats2half2_rn(p2, p3));
            }
            uint32_t bv2[8][2];
#pragma unroll
            for (int nt = 0; nt < 8; ++nt) {
                const uint32_t o = (uint32_t)(((nt * 8 + r) * VPITCH + kt * 16 + c2) * 2);
                bv2[nt][0] = *(const uint32_t*)(Vsh + o);
                bv2[nt][1] = *(const uint32_t*)(Vsh + o + 16);
            }
#pragma unroll
            for (int nt = 0; nt < 8; ++nt)
                mma16816(cacc[nt], aPh, bv2[nt]);
        }
    }

    // ---- epilogue: normalize, split to fp16 hi/lo, write ctx
    const float inv0 = 1.0f / l0, inv1 = 1.0f / l1;
    const int row0 = q0 + wid * 16 + r;
    const size_t ob = ((size_t)(b * Tt) + row0) * Dd + h * HDh;
#pragma unroll
    for (int nt = 0; nt < 8; ++nt) {
        const int col = nt * 8 + c2;
        const float v0 = cacc[nt][0] * inv0, v1 = cacc[nt][1] * inv0;
        const float v2 = cacc[nt][2] * inv1, v3 = cacc[nt][3] * inv1;
        const __half2 h01 = __floats2half2_rn(v0, v1);
        const __half2 h23 = __floats2half2_rn(v2, v3);
        const __half2 q01 = __floats2half2_rn(
            v0 - __half2float(__low2half(h01)), v1 - __half2float(__high2half(h01)));
        const __half2 q23 = __floats2half2_rn(
            v2 - __half2float(__low2half(h23)), v3 - __half2float(__high2half(h23)));
        *(uint32_t*)(och + ob + col)            = h2_bits(h01);
        *(uint32_t*)(ocl + ob + col)            = h2_bits(q01);
        *(uint32_t*)(och + ob + 8 * Dd + col)   = h2_bits(h23);
        *(uint32_t*)(ocl + ob + 8 * Dd + col)   = h2_bits(q23);
    }
}

// ---------------------------------------------------------------------------
extern "C" void kernel_launch(void* const* d_in, const int* in_sizes, int n_in,
                              void* d_out, int out_size)
{
    const float* x  = (const float*)d_in[0];
    const float* Wq = (const float*)d_in[1];
    const float* bq = (const float*)d_in[2];
    const float* Wk = (const float*)d_in[3];
    const float* bk = (const float*)d_in[4];
    const float* Wv = (const float*)d_in[5];
    const float* bv = (const float*)d_in[6];
    const float* Wo = (const float*)d_in[7];
    const float* bo = (const float*)d_in[8];
    const int* mask = (const int*)d_in[9];
    float* out = (float*)d_out;

    __half *xh, *xl, *qhp, *qlp, *khp, *vhp, *chp, *clp, *wh, *wl;
    cudaGetSymbolAddress((void**)&xh, g_xh);
    cudaGetSymbolAddress((void**)&xl, g_xl);
    cudaGetSymbolAddress((void**)&qhp, g_qh);
    cudaGetSymbolAddress((void**)&qlp, g_ql);
    cudaGetSymbolAddress((void**)&khp, g_kh);
    cudaGetSymbolAddress((void**)&vhp, g_vh);
    cudaGetSymbolAddress((void**)&chp, g_ch);
    cudaGetSymbolAddress((void**)&clp, g_cl);
    cudaGetSymbolAddress((void**)&wh, g_wh);
    cudaGetSymbolAddress((void**)&wl, g_wl);

    const size_t WSZ = (size_t)Dd * Dd;
    const int n4x = (Mm * Dd) / 4;
    const int n4w = (int)(WSZ / 4);

    // splits
    split_x_kernel<<<(n4x + 255) / 256, 256>>>(x, xh, xl, n4x);
    split_w4_kernel<<<(4 * n4w + 255) / 256, 256>>>(Wq, Wk, Wv, Wo, wh, wl, n4w);

    cudaFuncSetAttribute(gemm3p_bk32,
                         cudaFuncAttributeMaxDynamicSharedMemorySize, GSMEM_B);
    cudaFuncSetAttribute(gemm2p_bk64,
                         cudaFuncAttributeMaxDynamicSharedMemorySize, G2SMEM_B);
    dim3 ggrid(Dd / 128, Mm / 128);

    // Q projection: 3-pass BK32 -> fp16 hi/lo, pre-scaled 1/8
    gemm3p_bk32<<<ggrid, 256, GSMEM_B>>>(xh, xl, wh + 0 * WSZ, wl + 0 * WSZ, bq,
                                         qhp, qlp, 0.125f);
    // K,V projections: 2-pass BK64 -> single fp16
    gemm2p_bk64<<<ggrid, 256, G2SMEM_B>>>(xh, xl, wh + 1 * WSZ, bk, nullptr, khp);
    gemm2p_bk64<<<ggrid, 256, G2SMEM_B>>>(xh, xl, wh + 2 * WSZ, bv, nullptr, vhp);

    // fused attention (single-sync mainloop)
    cudaFuncSetAttribute(attn_mma_kernel,
                         cudaFuncAttributeMaxDynamicSharedMemorySize, AT_SMEM);
    attn_mma_kernel<<<dim3(Tt / 128, Hh, Bb), 256, AT_SMEM>>>(
        qhp, qlp, khp, vhp, mask, chp, clp);

    // Output projection: 2-pass BK64 -> fp32
    gemm2p_bk64<<<ggrid, 256, G2SMEM_B>>>(chp, clp, wh + 3 * WSZ, bo, out, nullptr);
}

// round 15
// speedup vs baseline: 1.0073x; 1.0073x over previous
#include <cuda_runtime.h>
#include <cuda_fp16.h>
#include <cstdint>

// Problem constants
#define Bb  4
#define Tt  2048
#define Dd  1024
#define Hh  16
#define HDh 64
#define Mm  (Bb * Tt)   // 8192 rows

// ---------------------------------------------------------------------------
// Scratch (device globals: allocation-free rule). All fp16.
// ---------------------------------------------------------------------------
__device__ __half g_xh[(size_t)Mm * Dd];
__device__ __half g_xl[(size_t)Mm * Dd];
__device__ __half g_qh[(size_t)Mm * Dd];
__device__ __half g_ql[(size_t)Mm * Dd];
__device__ __half g_kh[(size_t)Mm * Dd];          // K single-rounded
__device__ __half g_vh[(size_t)Mm * Dd];          // V single-rounded
__device__ __half g_ch[(size_t)Mm * Dd];
__device__ __half g_cl[(size_t)Mm * Dd];
__device__ __half g_wh[4 * (size_t)Dd * Dd];
__device__ __half g_wl[4 * (size_t)Dd * Dd];

// ---------------------------------------------------------------------------
// sm_100-base helpers: cp.async + mma.sync fp16 (tcgen05 unavailable here)
// ---------------------------------------------------------------------------
__device__ __forceinline__ uint32_t smem_to_u32(const void* p) {
    uint32_t a;
    asm("{ .reg .u64 t; cvta.to.shared.u64 t, %1; cvt.u32.u64 %0, t; }"
        : "=r"(a) : "l"(p));
    return a;
}
__device__ __forceinline__ void cp_async16(uint32_t smem_addr, const void* gptr) {
    asm volatile("cp.async.cg.shared.global [%0], [%1], 16;"
                 :: "r"(smem_addr), "l"(gptr));
}
__device__ __forceinline__ void cp_commit() {
    asm volatile("cp.async.commit_group;");
}
template <int N>
__device__ __forceinline__ void cp_wait() {
    asm volatile("cp.async.wait_group %0;" :: "n"(N));
}
// D += A*B, m16n8k16 fp16 in / fp32 accum; A row-major, B col-major
__device__ __forceinline__ void mma16816(float* d, const uint32_t* a, const uint32_t* b) {
    asm volatile(
        "mma.sync.aligned.m16n8k16.row.col.f32.f16.f16.f32 "
        "{%0,%1,%2,%3}, {%4,%5,%6,%7}, {%8,%9}, {%0,%1,%2,%3};"
        : "+f"(d[0]), "+f"(d[1]), "+f"(d[2]), "+f"(d[3])
        : "r"(a[0]), "r"(a[1]), "r"(a[2]), "r"(a[3]), "r"(b[0]), "r"(b[1]));
}
__device__ __forceinline__ uint32_t h2_bits(__half2 v) {
    union { __half2 h; uint32_t u; } cv; cv.h = v; return cv.u;
}
// hi/lo split of one float into two fp16
__device__ __forceinline__ void split_h(float v, __half& hi, __half& lo) {
    hi = __float2half_rn(v);
    lo = __float2half_rn(v - __half2float(hi));
}

// ---------------------------------------------------------------------------
// Split kernels (fp32 -> fp16 hi/lo)
// ---------------------------------------------------------------------------
__global__ __launch_bounds__(256) void split_x_kernel(
    const float* __restrict__ src,
    __half* __restrict__ hi, __half* __restrict__ lo, int n4)
{
    int i = blockIdx.x * blockDim.x + threadIdx.x;
    if (i >= n4) return;
    float4 v = ((const float4*)src)[i];
    __half h0, h1, h2, h3, l0, l1, l2, l3;
    split_h(v.x, h0, l0); split_h(v.y, h1, l1);
    split_h(v.z, h2, l2); split_h(v.w, h3, l3);
    union { __half b[4]; uint2 u; } ph, pl;
    ph.b[0] = h0; ph.b[1] = h1; ph.b[2] = h2; ph.b[3] = h3;
    pl.b[0] = l0; pl.b[1] = l1; pl.b[2] = l2; pl.b[3] = l3;
    ((uint2*)hi)[i] = ph.u;
    ((uint2*)lo)[i] = pl.u;
}

// all 4 weight matrices in one launch; dest arrays are contiguous per-matrix
__global__ __launch_bounds__(256) void split_w4_kernel(
    const float* __restrict__ w0, const float* __restrict__ w1,
    const float* __restrict__ w2, const float* __restrict__ w3,
    __half* __restrict__ hi, __half* __restrict__ lo, int n4_each)
{
    int i = blockIdx.x * blockDim.x + threadIdx.x;
    if (i >= 4 * n4_each) return;
    const int m = i / n4_each, j = i - m * n4_each;
    const float* src = (m == 0) ? w0 : (m == 1) ? w1 : (m == 2) ? w2 : w3;
    float4 v = ((const float4*)src)[j];
    __half h0, h1, h2, h3, l0, l1, l2, l3;
    split_h(v.x, h0, l0); split_h(v.y, h1, l1);
    split_h(v.z, h2, l2); split_h(v.w, h3, l3);
    union { __half b[4]; uint2 u; } ph, pl;
    ph.b[0] = h0; ph.b[1] = h1; ph.b[2] = h2; ph.b[3] = h3;
    pl.b[0] = l0; pl.b[1] = l1; pl.b[2] = l2; pl.b[3] = l3;
    ((uint2*)hi)[i] = ph.u;
    ((uint2*)lo)[i] = pl.u;
}

// ---------------------------------------------------------------------------
// 3-pass fp16 split GEMM (Q projection): C = (Ah+Al) @ (Bh+Bl)^T + bias,
// dropping Al*Bl. BK=32, double-buffered, single sync per chunk.
// Output: fp16 hi/lo, scaled.
// ---------------------------------------------------------------------------
#define GPITCH 40
#define GTILE_B (128 * GPITCH * 2)
#define GSTAGE_B (4 * GTILE_B)
#define GSMEM_B (2 * GSTAGE_B)

__global__ __launch_bounds__(256, 2) void gemm3p_bk32(
    const __half* __restrict__ Ah, const __half* __restrict__ Al,
    const __half* __restrict__ Bh, const __half* __restrict__ Bl,
    const float* __restrict__ bias,
    __half* __restrict__ Oh, __half* __restrict__ Ol, float scale)
{
    extern __shared__ __align__(128) uint8_t smem[];
    const int tid  = threadIdx.x;
    const int wid  = tid >> 5;
    const int lane = tid & 31;
    const int wm   = wid & 3;
    const int wn   = wid >> 2;
    const int gm0  = blockIdx.y * 128;
    const int gn0  = blockIdx.x * 128;
    const uint32_t sbase = smem_to_u32(smem);

    const __half* srcs[4] = { Ah, Al, Bh, Bl };

    auto issue = [&](int s, int c) {
        const int k0 = c * 32;
#pragma unroll
        for (int t = 0; t < 4; ++t) {
            const __half* src = srcs[t];
            const int rbase = (t < 2) ? gm0 : gn0;
#pragma unroll
            for (int j = 0; j < 2; ++j) {
                const int i = tid + j * 256;
                const int row = i >> 2, chunk = i & 3;
                const uint32_t sa = sbase + s * GSTAGE_B + t * GTILE_B
                                  + (uint32_t)(row * GPITCH + chunk * 8) * 2;
                const void* g = src + (size_t)(rbase + row) * Dd + k0 + chunk * 8;
                cp_async16(sa, g);
            }
        }
        cp_commit();
    };

    float acc[2][8][4];
#pragma unroll
    for (int mt = 0; mt < 2; ++mt)
#pragma unroll
        for (int nt = 0; nt < 8; ++nt)
#pragma unroll
            for (int q = 0; q < 4; ++q) acc[mt][nt][q] = 0.f;

    const int r   = lane >> 2;
    const int cp2 = (lane & 3) * 2;

    issue(0, 0);

    for (int c = 0; c < 32; ++c) {
        const int s = c & 1;
        cp_wait<0>();
        __syncthreads();
        if (c + 1 < 32) issue(s ^ 1, c + 1);

        const uint8_t* stg = smem + s * GSTAGE_B;
        const uint8_t* pAh = stg;
        const uint8_t* pAl = stg + GTILE_B;
        const uint8_t* pBh = stg + 2 * GTILE_B;
        const uint8_t* pBl = stg + 3 * GTILE_B;

#pragma unroll
        for (int ks = 0; ks < 2; ++ks) {
            const int kk = ks * 16;
            uint32_t ah[2][4], al[2][4];
#pragma unroll
            for (int mt = 0; mt < 2; ++mt) {
                const int row = wm * 32 + mt * 16 + r;
                const uint32_t o00 = (uint32_t)(row * GPITCH + kk + cp2) * 2;
                const uint32_t o10 = (uint32_t)((row + 8) * GPITCH + kk + cp2) * 2;
                ah[mt][0] = *(const uint32_t*)(pAh + o00);
                ah[mt][1] = *(const uint32_t*)(pAh + o10);
                ah[mt][2] = *(const uint32_t*)(pAh + o00 + 16);
                ah[mt][3] = *(const uint32_t*)(pAh + o10 + 16);
                al[mt][0] = *(const uint32_t*)(pAl + o00);
                al[mt][1] = *(const uint32_t*)(pAl + o10);
                al[mt][2] = *(const uint32_t*)(pAl + o00 + 16);
                al[mt][3] = *(const uint32_t*)(pAl + o10 + 16);
            }
#pragma unroll
            for (int nh = 0; nh < 2; ++nh) {
                uint32_t bh[4][2], bl[4][2];
#pragma unroll
                for (int nt = 0; nt < 4; ++nt) {
                    const int n = wn * 64 + (nh * 4 + nt) * 8 + r;
                    const uint32_t ob = (uint32_t)(n * GPITCH + kk + cp2) * 2;
                    bh[nt][0] = *(const uint32_t*)(pBh + ob);
                    bh[nt][1] = *(const uint32_t*)(pBh + ob + 16);
                    bl[nt][0] = *(const uint32_t*)(pBl + ob);
                    bl[nt][1] = *(const uint32_t*)(pBl + ob + 16);
                }
#pragma unroll
                for (int nt = 0; nt < 4; ++nt) {
                    mma16816(acc[0][nh * 4 + nt], ah[0], bh[nt]);
                    mma16816(acc[1][nh * 4 + nt], ah[1], bh[nt]);
                }
#pragma unroll
                for (int nt = 0; nt < 4; ++nt) {
                    mma16816(acc[0][nh * 4 + nt], al[0], bh[nt]);
                    mma16816(acc[1][nh * 4 + nt], al[1], bh[nt]);
                }
#pragma unroll
                for (int nt = 0; nt < 4; ++nt) {
                    mma16816(acc[0][nh * 4 + nt], ah[0], bl[nt]);
                    mma16816(acc[1][nh * 4 + nt], ah[1], bl[nt]);
                }
            }
        }
    }

    // Epilogue: scaled fp16 hi/lo
#pragma unroll
    for (int mt = 0; mt < 2; ++mt) {
        const int row0 = gm0 + wm * 32 + mt * 16 + r;
#pragma unroll
        for (int nt = 0; nt < 8; ++nt) {
            const int col = gn0 + wn * 64 + nt * 8 + cp2;
            const float b0 = bias[col], b1 = bias[col + 1];
            float v0 = (acc[mt][nt][0] + b0) * scale, v1 = (acc[mt][nt][1] + b1) * scale;
            float v2 = (acc[mt][nt][2] + b0) * scale, v3 = (acc[mt][nt][3] + b1) * scale;
            __half2 h01 = __floats2half2_rn(v0, v1);
            __half2 h23 = __floats2half2_rn(v2, v3);
            __half2 l01 = __floats2half2_rn(
                v0 - __half2float(__low2half(h01)), v1 - __half2float(__high2half(h01)));
            __half2 l23 = __floats2half2_rn(
                v2 - __half2float(__low2half(h23)), v3 - __half2float(__high2half(h23)));
            *(uint32_t*)(Oh + (size_t)row0 * Dd + col)       = h2_bits(h01);
            *(uint32_t*)(Ol + (size_t)row0 * Dd + col)       = h2_bits(l01);
            *(uint32_t*)(Oh + (size_t)(row0 + 8) * Dd + col) = h2_bits(h23);
            *(uint32_t*)(Ol + (size_t)(row0 + 8) * Dd + col) = h2_bits(l23);
        }
    }
}

// ---------------------------------------------------------------------------
// 2-pass fp16 split GEMM (K/V/O projections): C = (Ah+Al) @ Bh^T + bias.
// BK=64 (3 tiles/stage, 110.6 KB smem, 2 CTAs/SM), single sync per chunk.
// Output: fp16 single (Oh) or fp32 (Cf32).
// ---------------------------------------------------------------------------
#define G2PITCH 72
#define G2TILE_B (128 * G2PITCH * 2)      // 18432
#define G2STAGE_B (3 * G2TILE_B)          // 55296
#define G2SMEM_B (2 * G2STAGE_B)          // 110592

__global__ __launch_bounds__(256, 2) void gemm2p_bk64(
    const __half* __restrict__ Ah, const __half* __restrict__ Al,
    const __half* __restrict__ Bh,
    const float* __restrict__ bias,
    float* __restrict__ Cf32, __half* __restrict__ Oh)
{
    extern __shared__ __align__(128) uint8_t smem[];
    const int tid  = threadIdx.x;
    const int wid  = tid >> 5;
    const int lane = tid & 31;
    const int wm   = wid & 3;
    const int wn   = wid >> 2;
    const int gm0  = blockIdx.y * 128;
    const int gn0  = blockIdx.x * 128;
    const uint32_t sbase = smem_to_u32(smem);

    const __half* srcs[3] = { Ah, Al, Bh };

    auto issue = [&](int s, int c) {
        const int k0 = c * 64;
#pragma unroll
        for (int t = 0; t < 3; ++t) {
            const __half* src = srcs[t];
            const int rbase = (t < 2) ? gm0 : gn0;
#pragma unroll
            for (int j = 0; j < 4; ++j) {
                const int i = tid + j * 256;
                const int row = i >> 3, seg = i & 7;
                const uint32_t sa = sbase + s * G2STAGE_B + t * G2TILE_B
                                  + (uint32_t)(row * G2PITCH + seg * 8) * 2;
                const void* g = src + (size_t)(rbase + row) * Dd + k0 + seg * 8;
                cp_async16(sa, g);
            }
        }
        cp_commit();
    };

    float acc[2][8][4];
#pragma unroll
    for (int mt = 0; mt < 2; ++mt)
#pragma unroll
        for (int nt = 0; nt < 8; ++nt)
#pragma unroll
            for (int q = 0; q < 4; ++q) acc[mt][nt][q] = 0.f;

    const int r   = lane >> 2;
    const int cp2 = (lane & 3) * 2;

    issue(0, 0);

    for (int c = 0; c < 16; ++c) {
        const int s = c & 1;
        cp_wait<0>();
        __syncthreads();
        if (c + 1 < 16) issue(s ^ 1, c + 1);

        const uint8_t* stg = smem + s * G2STAGE_B;
        const uint8_t* pAh = stg;
        const uint8_t* pAl = stg + G2TILE_B;
        const uint8_t* pBh = stg + 2 * G2TILE_B;

#pragma unroll
        for (int ks = 0; ks < 4; ++ks) {
            const int kk = ks * 16;
            uint32_t ah[2][4], al[2][4];
#pragma unroll
            for (int mt = 0; mt < 2; ++mt) {
                const int row = wm * 32 + mt * 16 + r;
                const uint32_t o00 = (uint32_t)(row * G2PITCH + kk + cp2) * 2;
                const uint32_t o10 = (uint32_t)((row + 8) * G2PITCH + kk + cp2) * 2;
                ah[mt][0] = *(const uint32_t*)(pAh + o00);
                ah[mt][1] = *(const uint32_t*)(pAh + o10);
                ah[mt][2] = *(const uint32_t*)(pAh + o00 + 16);
                ah[mt][3] = *(const uint32_t*)(pAh + o10 + 16);
                al[mt][0] = *(const uint32_t*)(pAl + o00);
                al[mt][1] = *(const uint32_t*)(pAl + o10);
                al[mt][2] = *(const uint32_t*)(pAl + o00 + 16);
                al[mt][3] = *(const uint32_t*)(pAl + o10 + 16);
            }
#pragma unroll
            for (int nh = 0; nh < 2; ++nh) {
                uint32_t bh[4][2];
#pragma unroll
                for (int nt = 0; nt < 4; ++nt) {
                    const int n = wn * 64 + (nh * 4 + nt) * 8 + r;
                    const uint32_t ob = (uint32_t)(n * G2PITCH + kk + cp2) * 2;
                    bh[nt][0] = *(const uint32_t*)(pBh + ob);
                    bh[nt][1] = *(const uint32_t*)(pBh + ob + 16);
                }
#pragma unroll
                for (int nt = 0; nt < 4; ++nt) {
                    mma16816(acc[0][nh * 4 + nt], ah[0], bh[nt]);
                    mma16816(acc[1][nh * 4 + nt], ah[1], bh[nt]);
                }
#pragma unroll
                for (int nt = 0; nt < 4; ++nt) {
                    mma16816(acc[0][nh * 4 + nt], al[0], bh[nt]);
                    mma16816(acc[1][nh * 4 + nt], al[1], bh[nt]);
                }
            }
        }
    }

    // Epilogue
#pragma unroll
    for (int mt = 0; mt < 2; ++mt) {
        const int row0 = gm0 + wm * 32 + mt * 16 + r;
#pragma unroll
        for (int nt = 0; nt < 8; ++nt) {
            const int col = gn0 + wn * 64 + nt * 8 + cp2;
            const float b0 = bias[col], b1 = bias[col + 1];
            float v0 = acc[mt][nt][0] + b0, v1 = acc[mt][nt][1] + b1;
            float v2 = acc[mt][nt][2] + b0, v3 = acc[mt][nt][3] + b1;
            if (Cf32) {
                float2 w0, w1;
                w0.x = v0; w0.y = v1; w1.x = v2; w1.y = v3;
                *(float2*)(Cf32 + (size_t)row0 * Dd + col)       = w0;
                *(float2*)(Cf32 + (size_t)(row0 + 8) * Dd + col) = w1;
            } else {
                __half2 h01 = __floats2half2_rn(v0, v1);
                __half2 h23 = __floats2half2_rn(v2, v3);
                *(uint32_t*)(Oh + (size_t)row0 * Dd + col)       = h2_bits(h01);
                *(uint32_t*)(Oh + (size_t)(row0 + 8) * Dd + col) = h2_bits(h23);
            }
        }
    }
}

// ---------------------------------------------------------------------------
// Flash attention, fp16 mma.sync (R13 base structure).
// S = (Qh+Ql) @ K (2 MMAs); PV = Ph @ Vh (1 MMA, l exact fp32).
// R15: exp/pack interleaved with PV MMA issue per kt (MUFU overlaps tensor);
// row-sum order preserved (bit-exact vs R13), l updated after the PV loop.
// Grid (T/128, H, B), 256 threads = 8 warps; warp w owns q rows [16w,16w+16).
// Q pre-scaled by 1/8 in the Q projection epilogue.
// ---------------------------------------------------------------------------
#define QPITCH 72     // fp16; pitch%64==8 -> conflict-free frag loads
#define VPITCH 136
#define AT_QH   0
#define AT_QL   18432
#define AT_K0   36864          // + s*18432 (K hi only)
#define AT_VH   73728
#define AT_BIAS 91136
#define AT_SMEM 91648

__global__ __launch_bounds__(256, 1) void attn_mma_kernel(
    const __half* __restrict__ qh, const __half* __restrict__ ql,
    const __half* __restrict__ kh,
    const __half* __restrict__ vh,
    const int* __restrict__ mask,
    __half* __restrict__ och, __half* __restrict__ ocl)
{
    extern __shared__ __align__(128) uint8_t sm[];
    const uint32_t sb = smem_to_u32(sm);
    const int tid = threadIdx.x, wid = tid >> 5, lane = tid & 31;
    const int r = lane >> 2, c2 = (lane & 3) * 2;
    const int b = blockIdx.z, h = blockIdx.y;
    const int q0 = blockIdx.x * 128;
    const size_t gq = ((size_t)(b * Tt + q0)) * Dd + h * HDh;
    const size_t gk = ((size_t)(b * Tt)) * Dd + h * HDh;
    const int* mb = mask + b * Tt;

    // ---- preamble: stage Q (hi/lo) and K tile 0 via cp.async
#pragma unroll
    for (int j = 0; j < 4; ++j) {
        const int i = tid + j * 256, row = i >> 3, seg = i & 7;
        const uint32_t so = (uint32_t)((row * QPITCH + seg * 8) * 2);
        const size_t go = (size_t)row * Dd + seg * 8;
        cp_async16(sb + AT_QH + so, qh + gq + go);
        cp_async16(sb + AT_QL + so, ql + gq + go);
        cp_async16(sb + AT_K0 + so, kh + gk + go);
    }
    cp_commit();

    // ---- V register prefetch: thread -> kv rows 2vj,2vj+1, hd quarter vq*16
    const int vj = tid >> 2;
    const int vq = tid & 3;
    uint4 vr_h[2][2];
#pragma unroll
    for (int rr = 0; rr < 2; ++rr) {
        const size_t g = ((size_t)(b * Tt + 2 * vj + rr)) * Dd + h * HDh + vq * 16;
        vr_h[rr][0] = *(const uint4*)(vh + g);
        vr_h[rr][1] = *(const uint4*)(vh + g + 8);
    }

    float cacc[8][4];
#pragma unroll
    for (int nt = 0; nt < 8; ++nt)
#pragma unroll
        for (int q = 0; q < 4; ++q) cacc[nt][q] = 0.f;
    float m0 = -1e30f, m1 = -1e30f, l0 = 0.f, l1 = 0.f;
    uint32_t qAh[4][4], qAl[4][4];

    for (int c = 0; c < 16; ++c) {
        const int kv0 = c * 128;
        const int s = c & 1;
        cp_wait<0>();
        __syncthreads();   // K(c) visible; prev iter's Vt/K reads done

        // stage V^T(c) from regs (packed pairs via prmt) + mask bias
#pragma unroll
        for (int w = 0; w < 8; ++w) {
            const uint32_t a0 = ((const uint32_t*)&vr_h[0])[w];
            const uint32_t a1 = ((const uint32_t*)&vr_h[1])[w];
            const int hd = vq * 16 + 2 * w;
            *(uint32_t*)(sm + AT_VH + ((hd)     * VPITCH + 2 * vj) * 2) = __byte_perm(a0, a1, 0x5410);
            *(uint32_t*)(sm + AT_VH + ((hd + 1) * VPITCH + 2 * vj) * 2) = __byte_perm(a0, a1, 0x7632);
        }
        if (tid < 128)
            ((float*)(sm + AT_BIAS))[tid] = (mb[kv0 + tid] == 0) ? -1e30f : 0.f;

        // prefetch V(c+1) into regs
        if (c + 1 < 16) {
#pragma unroll
            for (int rr = 0; rr < 2; ++rr) {
                const size_t g = ((size_t)(b * Tt + kv0 + 128 + 2 * vj + rr)) * Dd + h * HDh + vq * 16;
                vr_h[rr][0] = *(const uint4*)(vh + g);
                vr_h[rr][1] = *(const uint4*)(vh + g + 8);
            }
        }

        if (c == 0) {   // Q A-frags, hoisted
#pragma unroll
            for (int kt = 0; kt < 4; ++kt) {
                const uint32_t o  = (uint32_t)(((wid * 16 + r) * QPITCH + kt * 16 + c2) * 2);
                const uint32_t o8 = o + 8 * QPITCH * 2;
                qAh[kt][0] = *(const uint32_t*)(sm + AT_QH + o);
                qAh[kt][1] = *(const uint32_t*)(sm + AT_QH + o8);
                qAh[kt][2] = *(const uint32_t*)(sm + AT_QH + o + 16);
                qAh[kt][3] = *(const uint32_t*)(sm + AT_QH + o8 + 16);
                qAl[kt][0] = *(const uint32_t*)(sm + AT_QL + o);
                qAl[kt][1] = *(const uint32_t*)(sm + AT_QL + o8);
                qAl[kt][2] = *(const uint32_t*)(sm + AT_QL + o + 16);
                qAl[kt][3] = *(const uint32_t*)(sm + AT_QL + o8 + 16);
            }
        }

        // prefetch K(c+1) -> stage s^1 (safe: all warps past sync above)
        if (c + 1 < 16) {
#pragma unroll
            for (int j = 0; j < 4; ++j) {
                const int i = tid + j * 256, row = i >> 3, seg = i & 7;
                const uint32_t so = (uint32_t)((row * QPITCH + seg * 8) * 2);
                const size_t g = gk + (size_t)(kv0 + 128 + row) * Dd + seg * 8;
                cp_async16(sb + AT_K0 + (s ^ 1) * 18432 + so, kh + g);
            }
        }
        cp_commit();
        __syncthreads();   // Vt(c), bias visible

        // ---- S = (Qh+Ql) K^T  (pass-ordered, distance-8 acc reuse)
        const uint8_t* Ksh = sm + AT_K0 + s * 18432;
        float sacc[16][4];
#pragma unroll
        for (int nt = 0; nt < 16; ++nt)
#pragma unroll
            for (int q = 0; q < 4; ++q) sacc[nt][q] = 0.f;
#pragma unroll
        for (int kt = 0; kt < 4; ++kt) {
#pragma unroll
            for (int nh = 0; nh < 2; ++nh) {
                uint32_t bk2[8][2];
#pragma unroll
                for (int nt = 0; nt < 8; ++nt) {
                    const uint32_t o = (uint32_t)((((nh * 8 + nt) * 8 + r) * QPITCH + kt * 16 + c2) * 2);
                    bk2[nt][0] = *(const uint32_t*)(Ksh + o);
                    bk2[nt][1] = *(const uint32_t*)(Ksh + o + 16);
                }
#pragma unroll
                for (int nt = 0; nt < 8; ++nt)
                    mma16816(sacc[nh * 8 + nt], qAh[kt], bk2[nt]);
#pragma unroll
                for (int nt = 0; nt < 8; ++nt)
                    mma16816(sacc[nh * 8 + nt], qAl[kt], bk2[nt]);
            }
        }

        // ---- mask bias + row max (global over the KV tile)
        const float* bias = (const float*)(sm + AT_BIAS);
        float tmax0 = -1e30f, tmax1 = -1e30f;
#pragma unroll
        for (int nt = 0; nt < 16; ++nt) {
            const float2 bv = *(const float2*)(bias + nt * 8 + c2);
            sacc[nt][0] += bv.x; sacc[nt][1] += bv.y;
            sacc[nt][2] += bv.x; sacc[nt][3] += bv.y;
            tmax0 = fmaxf(tmax0, fmaxf(sacc[nt][0], sacc[nt][1]));
            tmax1 = fmaxf(tmax1, fmaxf(sacc[nt][2], sacc[nt][3]));
        }
        tmax0 = fmaxf(tmax0, __shfl_xor_sync(0xffffffffu, tmax0, 1));
        tmax0 = fmaxf(tmax0, __shfl_xor_sync(0xffffffffu, tmax0, 2));
        tmax1 = fmaxf(tmax1, __shfl_xor_sync(0xffffffffu, tmax1, 1));
        tmax1 = fmaxf(tmax1, __shfl_xor_sync(0xffffffffu, tmax1, 2));
        const float mn0 = fmaxf(m0, tmax0), mn1 = fmaxf(m1, tmax1);
        const float al0 = __expf(m0 - mn0), al1 = __expf(m1 - mn1);
        m0 = mn0; m1 = mn1;
#pragma unroll
        for (int nt = 0; nt < 8; ++nt) {
            cacc[nt][0] *= al0; cacc[nt][1] *= al0;
            cacc[nt][2] *= al1; cacc[nt][3] *= al1;
        }

        // ---- R15: interleaved exp/pack + PV MMA per kt (MUFU || tensor).
        // Row-sum accumulation order matches R13 (tiles ascending) -> bit-exact.
        float rs0 = 0.f, rs1 = 0.f;
#pragma unroll
        for (int kt = 0; kt < 8; ++kt) {
            uint32_t aPh[4];
#pragma unroll
            for (int u = 0; u < 2; ++u) {
                const int t2 = 2 * kt + u;
                sacc[t2][0] = __expf(sacc[t2][0] - mn0);
                sacc[t2][1] = __expf(sacc[t2][1] - mn0);
                sacc[t2][2] = __expf(sacc[t2][2] - mn1);
                sacc[t2][3] = __expf(sacc[t2][3] - mn1);
                rs0 += sacc[t2][0] + sacc[t2][1];
                rs1 += sacc[t2][2] + sacc[t2][3];
                aPh[2 * u + 0] = h2_bits(__floats2half2_rn(sacc[t2][0], sacc[t2][1]));
                aPh[2 * u + 1] = h2_bits(__floats2half2_rn(sacc[t2][2], sacc[t2][3]));
            }
            uint32_t bv2[8][2];
#pragma unroll
            for (int nt = 0; nt < 8; ++nt) {
                const uint32_t o = (uint32_t)(((nt * 8 + r) * VPITCH + kt * 16 + c2) * 2);
                bv2[nt][0] = *(const uint32_t*)(sm + AT_VH + o);
                bv2[nt][1] = *(const uint32_t*)(sm + AT_VH + o + 16);
            }
#pragma unroll
            for (int nt = 0; nt < 8; ++nt)
                mma16816(cacc[nt], aPh, bv2[nt]);
        }

        // ---- l update (after PV; l not used inside)
        rs0 += __shfl_xor_sync(0xffffffffu, rs0, 1);
        rs0 += __shfl_xor_sync(0xffffffffu, rs0, 2);
        rs1 += __shfl_xor_sync(0xffffffffu, rs1, 1);
        rs1 += __shfl_xor_sync(0xffffffffu, rs1, 2);
        l0 = l0 * al0 + rs0;
        l1 = l1 * al1 + rs1;
    }

    // ---- epilogue: normalize, split to fp16 hi/lo, write ctx
    const float inv0 = 1.0f / l0, inv1 = 1.0f / l1;
    const int row0 = q0 + wid * 16 + r;
    const size_t ob = ((size_t)(b * Tt) + row0) * Dd + h * HDh;
#pragma unroll
    for (int nt = 0; nt < 8; ++nt) {
        const int col = nt * 8 + c2;
        const float v0 = cacc[nt][0] * inv0, v1 = cacc[nt][1] * inv0;
        const float v2 = cacc[nt][2] * inv1, v3 = cacc[nt][3] * inv1;
        const __half2 h01 = __floats2half2_rn(v0, v1);
        const __half2 h23 = __floats2half2_rn(v2, v3);
        const __half2 q01 = __floats2half2_rn(
            v0 - __half2float(__low2half(h01)), v1 - __half2float(__high2half(h01)));
        const __half2 q23 = __floats2half2_rn(
            v2 - __half2float(__low2half(h23)), v3 - __half2float(__high2half(h23)));
        *(uint32_t*)(och + ob + col)            = h2_bits(h01);
        *(uint32_t*)(ocl + ob + col)            = h2_bits(q01);
        *(uint32_t*)(och + ob + 8 * Dd + col)   = h2_bits(h23);
        *(uint32_t*)(ocl + ob + 8 * Dd + col)   = h2_bits(q23);
    }
}

// ---------------------------------------------------------------------------
extern "C" void kernel_launch(void* const* d_in, const int* in_sizes, int n_in,
                              void* d_out, int out_size)
{
    const float* x  = (const float*)d_in[0];
    const float* Wq = (const float*)d_in[1];
    const float* bq = (const float*)d_in[2];
    const float* Wk = (const float*)d_in[3];
    const float* bk = (const float*)d_in[4];
    const float* Wv = (const float*)d_in[5];
    const float* bv = (const float*)d_in[6];
    const float* Wo = (const float*)d_in[7];
    const float* bo = (const float*)d_in[8];
    const int* mask = (const int*)d_in[9];
    float* out = (float*)d_out;

    __half *xh, *xl, *qhp, *qlp, *khp, *vhp, *chp, *clp, *wh, *wl;
    cudaGetSymbolAddress((void**)&xh, g_xh);
    cudaGetSymbolAddress((void**)&xl, g_xl);
    cudaGetSymbolAddress((void**)&qhp, g_qh);
    cudaGetSymbolAddress((void**)&qlp, g_ql);
    cudaGetSymbolAddress((void**)&khp, g_kh);
    cudaGetSymbolAddress((void**)&vhp, g_vh);
    cudaGetSymbolAddress((void**)&chp, g_ch);
    cudaGetSymbolAddress((void**)&clp, g_cl);
    cudaGetSymbolAddress((void**)&wh, g_wh);
    cudaGetSymbolAddress((void**)&wl, g_wl);

    const size_t WSZ = (size_t)Dd * Dd;
    const int n4x = (Mm * Dd) / 4;
    const int n4w = (int)(WSZ / 4);

    // splits
    split_x_kernel<<<(n4x + 255) / 256, 256>>>(x, xh, xl, n4x);
    split_w4_kernel<<<(4 * n4w + 255) / 256, 256>>>(Wq, Wk, Wv, Wo, wh, wl, n4w);

    cudaFuncSetAttribute(gemm3p_bk32,
                         cudaFuncAttributeMaxDynamicSharedMemorySize, GSMEM_B);
    cudaFuncSetAttribute(gemm2p_bk64,
                         cudaFuncAttributeMaxDynamicSharedMemorySize, G2SMEM_B);
    dim3 ggrid(Dd / 128, Mm / 128);

    // Q projection: 3-pass BK32 -> fp16 hi/lo, pre-scaled 1/8
    gemm3p_bk32<<<ggrid, 256, GSMEM_B>>>(xh, xl, wh + 0 * WSZ, wl + 0 * WSZ, bq,
                                         qhp, qlp, 0.125f);
    // K,V projections: 2-pass BK64 -> single fp16
    gemm2p_bk64<<<ggrid, 256, G2SMEM_B>>>(xh, xl, wh + 1 * WSZ, bk, nullptr, khp);
    gemm2p_bk64<<<ggrid, 256, G2SMEM_B>>>(xh, xl, wh + 2 * WSZ, bv, nullptr, vhp);

    // fused attention
    cudaFuncSetAttribute(attn_mma_kernel,
                         cudaFuncAttributeMaxDynamicSharedMemorySize, AT_SMEM);
    attn_mma_kernel<<<dim3(Tt / 128, Hh, Bb), 256, AT_SMEM>>>(
        qhp, qlp, khp, vhp, mask, chp, clp);

    // Output projection: 2-pass BK64 -> fp32
    gemm2p_bk64<<<ggrid, 256, G2SMEM_B>>>(chp, clp, wh + 3 * WSZ, bo, out, nullptr);
}

// round 16
// speedup vs baseline: 1.0495x; 1.0419x over previous
#include <cuda_runtime.h>
#include <cuda_fp16.h>
#include <cstdint>

// Problem constants
#define Bb  4
#define Tt  2048
#define Dd  1024
#define Hh  16
#define HDh 64
#define Mm  (Bb * Tt)   // 8192 rows

// ---------------------------------------------------------------------------
// Scratch (device globals: allocation-free rule). All fp16.
// ---------------------------------------------------------------------------
__device__ __half g_xh[(size_t)Mm * Dd];
__device__ __half g_xl[(size_t)Mm * Dd];
__device__ __half g_qh[(size_t)Mm * Dd];
__device__ __half g_ql[(size_t)Mm * Dd];
__device__ __half g_kh[(size_t)Mm * Dd];          // K single-rounded
__device__ __half g_vh[(size_t)Mm * Dd];          // V single-rounded
__device__ __half g_ch[(size_t)Mm * Dd];          // ctx single-rounded (R16)
__device__ __half g_wh[4 * (size_t)Dd * Dd];
__device__ __half g_wl[4 * (size_t)Dd * Dd];

// ---------------------------------------------------------------------------
// sm_100-base helpers: cp.async + mma.sync fp16 (tcgen05 unavailable here)
// ---------------------------------------------------------------------------
__device__ __forceinline__ uint32_t smem_to_u32(const void* p) {
    uint32_t a;
    asm("{ .reg .u64 t; cvta.to.shared.u64 t, %1; cvt.u32.u64 %0, t; }"
        : "=r"(a) : "l"(p));
    return a;
}
__device__ __forceinline__ void cp_async16(uint32_t smem_addr, const void* gptr) {
    asm volatile("cp.async.cg.shared.global [%0], [%1], 16;"
                 :: "r"(smem_addr), "l"(gptr));
}
__device__ __forceinline__ void cp_commit() {
    asm volatile("cp.async.commit_group;");
}
template <int N>
__device__ __forceinline__ void cp_wait() {
    asm volatile("cp.async.wait_group %0;" :: "n"(N));
}
// D += A*B, m16n8k16 fp16 in / fp32 accum; A row-major, B col-major
__device__ __forceinline__ void mma16816(float* d, const uint32_t* a, const uint32_t* b) {
    asm volatile(
        "mma.sync.aligned.m16n8k16.row.col.f32.f16.f16.f32 "
        "{%0,%1,%2,%3}, {%4,%5,%6,%7}, {%8,%9}, {%0,%1,%2,%3};"
        : "+f"(d[0]), "+f"(d[1]), "+f"(d[2]), "+f"(d[3])
        : "r"(a[0]), "r"(a[1]), "r"(a[2]), "r"(a[3]), "r"(b[0]), "r"(b[1]));
}
__device__ __forceinline__ uint32_t h2_bits(__half2 v) {
    union { __half2 h; uint32_t u; } cv; cv.h = v; return cv.u;
}
// hi/lo split of one float into two fp16
__device__ __forceinline__ void split_h(float v, __half& hi, __half& lo) {
    hi = __float2half_rn(v);
    lo = __float2half_rn(v - __half2float(hi));
}

// ---------------------------------------------------------------------------
// Split kernels (fp32 -> fp16 hi/lo)
// ---------------------------------------------------------------------------
__global__ __launch_bounds__(256) void split_x_kernel(
    const float* __restrict__ src,
    __half* __restrict__ hi, __half* __restrict__ lo, int n4)
{
    int i = blockIdx.x * blockDim.x + threadIdx.x;
    if (i >= n4) return;
    float4 v = ((const float4*)src)[i];
    __half h0, h1, h2, h3, l0, l1, l2, l3;
    split_h(v.x, h0, l0); split_h(v.y, h1, l1);
    split_h(v.z, h2, l2); split_h(v.w, h3, l3);
    union { __half b[4]; uint2 u; } ph, pl;
    ph.b[0] = h0; ph.b[1] = h1; ph.b[2] = h2; ph.b[3] = h3;
    pl.b[0] = l0; pl.b[1] = l1; pl.b[2] = l2; pl.b[3] = l3;
    ((uint2*)hi)[i] = ph.u;
    ((uint2*)lo)[i] = pl.u;
}

// all 4 weight matrices in one launch; dest arrays are contiguous per-matrix
__global__ __launch_bounds__(256) void split_w4_kernel(
    const float* __restrict__ w0, const float* __restrict__ w1,
    const float* __restrict__ w2, const float* __restrict__ w3,
    __half* __restrict__ hi, __half* __restrict__ lo, int n4_each)
{
    int i = blockIdx.x * blockDim.x + threadIdx.x;
    if (i >= 4 * n4_each) return;
    const int m = i / n4_each, j = i - m * n4_each;
    const float* src = (m == 0) ? w0 : (m == 1) ? w1 : (m == 2) ? w2 : w3;
    float4 v = ((const float4*)src)[j];
    __half h0, h1, h2, h3, l0, l1, l2, l3;
    split_h(v.x, h0, l0); split_h(v.y, h1, l1);
    split_h(v.z, h2, l2); split_h(v.w, h3, l3);
    union { __half b[4]; uint2 u; } ph, pl;
    ph.b[0] = h0; ph.b[1] = h1; ph.b[2] = h2; ph.b[3] = h3;
    pl.b[0] = l0; pl.b[1] = l1; pl.b[2] = l2; pl.b[3] = l3;
    ((uint2*)hi)[i] = ph.u;
    ((uint2*)lo)[i] = pl.u;
}

// ---------------------------------------------------------------------------
// 3-pass fp16 split GEMM (Q projection): C = (Ah+Al) @ (Bh+Bl)^T + bias,
// dropping Al*Bl. BK=32, double-buffered, single sync per chunk.
// Output: fp16 hi/lo, scaled.
// ---------------------------------------------------------------------------
#define GPITCH 40
#define GTILE_B (128 * GPITCH * 2)
#define GSTAGE_B (4 * GTILE_B)
#define GSMEM_B (2 * GSTAGE_B)

__global__ __launch_bounds__(256, 2) void gemm3p_bk32(
    const __half* __restrict__ Ah, const __half* __restrict__ Al,
    const __half* __restrict__ Bh, const __half* __restrict__ Bl,
    const float* __restrict__ bias,
    __half* __restrict__ Oh, __half* __restrict__ Ol, float scale)
{
    extern __shared__ __align__(128) uint8_t smem[];
    const int tid  = threadIdx.x;
    const int wid  = tid >> 5;
    const int lane = tid & 31;
    const int wm   = wid & 3;
    const int wn   = wid >> 2;
    const int gm0  = blockIdx.y * 128;
    const int gn0  = blockIdx.x * 128;
    const uint32_t sbase = smem_to_u32(smem);

    const __half* srcs[4] = { Ah, Al, Bh, Bl };

    auto issue = [&](int s, int c) {
        const int k0 = c * 32;
#pragma unroll
        for (int t = 0; t < 4; ++t) {
            const __half* src = srcs[t];
            const int rbase = (t < 2) ? gm0 : gn0;
#pragma unroll
            for (int j = 0; j < 2; ++j) {
                const int i = tid + j * 256;
                const int row = i >> 2, chunk = i & 3;
                const uint32_t sa = sbase + s * GSTAGE_B + t * GTILE_B
                                  + (uint32_t)(row * GPITCH + chunk * 8) * 2;
                const void* g = src + (size_t)(rbase + row) * Dd + k0 + chunk * 8;
                cp_async16(sa, g);
            }
        }
        cp_commit();
    };

    float acc[2][8][4];
#pragma unroll
    for (int mt = 0; mt < 2; ++mt)
#pragma unroll
        for (int nt = 0; nt < 8; ++nt)
#pragma unroll
            for (int q = 0; q < 4; ++q) acc[mt][nt][q] = 0.f;

    const int r   = lane >> 2;
    const int cp2 = (lane & 3) * 2;

    issue(0, 0);

    for (int c = 0; c < 32; ++c) {
        const int s = c & 1;
        cp_wait<0>();
        __syncthreads();
        if (c + 1 < 32) issue(s ^ 1, c + 1);

        const uint8_t* stg = smem + s * GSTAGE_B;
        const uint8_t* pAh = stg;
        const uint8_t* pAl = stg + GTILE_B;
        const uint8_t* pBh = stg + 2 * GTILE_B;
        const uint8_t* pBl = stg + 3 * GTILE_B;

#pragma unroll
        for (int ks = 0; ks < 2; ++ks) {
            const int kk = ks * 16;
            uint32_t ah[2][4], al[2][4];
#pragma unroll
            for (int mt = 0; mt < 2; ++mt) {
                const int row = wm * 32 + mt * 16 + r;
                const uint32_t o00 = (uint32_t)(row * GPITCH + kk + cp2) * 2;
                const uint32_t o10 = (uint32_t)((row + 8) * GPITCH + kk + cp2) * 2;
                ah[mt][0] = *(const uint32_t*)(pAh + o00);
                ah[mt][1] = *(const uint32_t*)(pAh + o10);
                ah[mt][2] = *(const uint32_t*)(pAh + o00 + 16);
                ah[mt][3] = *(const uint32_t*)(pAh + o10 + 16);
                al[mt][0] = *(const uint32_t*)(pAl + o00);
                al[mt][1] = *(const uint32_t*)(pAl + o10);
                al[mt][2] = *(const uint32_t*)(pAl + o00 + 16);
                al[mt][3] = *(const uint32_t*)(pAl + o10 + 16);
            }
#pragma unroll
            for (int nh = 0; nh < 2; ++nh) {
                uint32_t bh[4][2], bl[4][2];
#pragma unroll
                for (int nt = 0; nt < 4; ++nt) {
                    const int n = wn * 64 + (nh * 4 + nt) * 8 + r;
                    const uint32_t ob = (uint32_t)(n * GPITCH + kk + cp2) * 2;
                    bh[nt][0] = *(const uint32_t*)(pBh + ob);
                    bh[nt][1] = *(const uint32_t*)(pBh + ob + 16);
                    bl[nt][0] = *(const uint32_t*)(pBl + ob);
                    bl[nt][1] = *(const uint32_t*)(pBl + ob + 16);
                }
#pragma unroll
                for (int nt = 0; nt < 4; ++nt) {
                    mma16816(acc[0][nh * 4 + nt], ah[0], bh[nt]);
                    mma16816(acc[1][nh * 4 + nt], ah[1], bh[nt]);
                }
#pragma unroll
                for (int nt = 0; nt < 4; ++nt) {
                    mma16816(acc[0][nh * 4 + nt], al[0], bh[nt]);
                    mma16816(acc[1][nh * 4 + nt], al[1], bh[nt]);
                }
#pragma unroll
                for (int nt = 0; nt < 4; ++nt) {
                    mma16816(acc[0][nh * 4 + nt], ah[0], bl[nt]);
                    mma16816(acc[1][nh * 4 + nt], ah[1], bl[nt]);
                }
            }
        }
    }

    // Epilogue: scaled fp16 hi/lo
#pragma unroll
    for (int mt = 0; mt < 2; ++mt) {
        const int row0 = gm0 + wm * 32 + mt * 16 + r;
#pragma unroll
        for (int nt = 0; nt < 8; ++nt) {
            const int col = gn0 + wn * 64 + nt * 8 + cp2;
            const float b0 = bias[col], b1 = bias[col + 1];
            float v0 = (acc[mt][nt][0] + b0) * scale, v1 = (acc[mt][nt][1] + b1) * scale;
            float v2 = (acc[mt][nt][2] + b0) * scale, v3 = (acc[mt][nt][3] + b1) * scale;
            __half2 h01 = __floats2half2_rn(v0, v1);
            __half2 h23 = __floats2half2_rn(v2, v3);
            __half2 l01 = __floats2half2_rn(
                v0 - __half2float(__low2half(h01)), v1 - __half2float(__high2half(h01)));
            __half2 l23 = __floats2half2_rn(
                v2 - __half2float(__low2half(h23)), v3 - __half2float(__high2half(h23)));
            *(uint32_t*)(Oh + (size_t)row0 * Dd + col)       = h2_bits(h01);
            *(uint32_t*)(Ol + (size_t)row0 * Dd + col)       = h2_bits(l01);
            *(uint32_t*)(Oh + (size_t)(row0 + 8) * Dd + col) = h2_bits(h23);
            *(uint32_t*)(Ol + (size_t)(row0 + 8) * Dd + col) = h2_bits(l23);
        }
    }
}

// ---------------------------------------------------------------------------
// 1/2-pass fp16 split GEMM (K/V/O projections): C = (Ah[+Al]) @ Bh^T + bias.
// BK=64, double-buffered, single sync per chunk. use_al selects 2-pass.
// Output: fp16 single (Oh) or fp32 (Cf32).
// ---------------------------------------------------------------------------
#define G2PITCH 72
#define G2TILE_B (128 * G2PITCH * 2)      // 18432
#define G2STAGE_B (3 * G2TILE_B)          // 55296
#define G2SMEM_B (2 * G2STAGE_B)          // 110592

__global__ __launch_bounds__(256, 2) void gemm2p_bk64(
    const __half* __restrict__ Ah, const __half* __restrict__ Al,
    const __half* __restrict__ Bh,
    const float* __restrict__ bias,
    float* __restrict__ Cf32, __half* __restrict__ Oh, int use_al)
{
    extern __shared__ __align__(128) uint8_t smem[];
    const int tid  = threadIdx.x;
    const int wid  = tid >> 5;
    const int lane = tid & 31;
    const int wm   = wid & 3;
    const int wn   = wid >> 2;
    const int gm0  = blockIdx.y * 128;
    const int gn0  = blockIdx.x * 128;
    const uint32_t sbase = smem_to_u32(smem);

    const __half* srcs[3] = { Ah, Al, Bh };

    auto issue = [&](int s, int c) {
        const int k0 = c * 64;
#pragma unroll
        for (int t = 0; t < 3; ++t) {
            if (t == 1 && !use_al) continue;
            const __half* src = srcs[t];
            const int rbase = (t < 2) ? gm0 : gn0;
#pragma unroll
            for (int j = 0; j < 4; ++j) {
                const int i = tid + j * 256;
                const int row = i >> 3, seg = i & 7;
                const uint32_t sa = sbase + s * G2STAGE_B + t * G2TILE_B
                                  + (uint32_t)(row * G2PITCH + seg * 8) * 2;
                const void* g = src + (size_t)(rbase + row) * Dd + k0 + seg * 8;
                cp_async16(sa, g);
            }
        }
        cp_commit();
    };

    float acc[2][8][4];
#pragma unroll
    for (int mt = 0; mt < 2; ++mt)
#pragma unroll
        for (int nt = 0; nt < 8; ++nt)
#pragma unroll
            for (int q = 0; q < 4; ++q) acc[mt][nt][q] = 0.f;

    const int r   = lane >> 2;
    const int cp2 = (lane & 3) * 2;

    issue(0, 0);

    for (int c = 0; c < 16; ++c) {
        const int s = c & 1;
        cp_wait<0>();
        __syncthreads();
        if (c + 1 < 16) issue(s ^ 1, c + 1);

        const uint8_t* stg = smem + s * G2STAGE_B;
        const uint8_t* pAh = stg;
        const uint8_t* pAl = stg + G2TILE_B;
        const uint8_t* pBh = stg + 2 * G2TILE_B;

#pragma unroll
        for (int ks = 0; ks < 4; ++ks) {
            const int kk = ks * 16;
            uint32_t ah[2][4], al[2][4];
#pragma unroll
            for (int mt = 0; mt < 2; ++mt) {
                const int row = wm * 32 + mt * 16 + r;
                const uint32_t o00 = (uint32_t)(row * G2PITCH + kk + cp2) * 2;
                const uint32_t o10 = (uint32_t)((row + 8) * G2PITCH + kk + cp2) * 2;
                ah[mt][0] = *(const uint32_t*)(pAh + o00);
                ah[mt][1] = *(const uint32_t*)(pAh + o10);
                ah[mt][2] = *(const uint32_t*)(pAh + o00 + 16);
                ah[mt][3] = *(const uint32_t*)(pAh + o10 + 16);
                if (use_al) {
                    al[mt][0] = *(const uint32_t*)(pAl + o00);
                    al[mt][1] = *(const uint32_t*)(pAl + o10);
                    al[mt][2] = *(const uint32_t*)(pAl + o00 + 16);
                    al[mt][3] = *(const uint32_t*)(pAl + o10 + 16);
                }
            }
#pragma unroll
            for (int nh = 0; nh < 2; ++nh) {
                uint32_t bh[4][2];
#pragma unroll
                for (int nt = 0; nt < 4; ++nt) {
                    const int n = wn * 64 + (nh * 4 + nt) * 8 + r;
                    const uint32_t ob = (uint32_t)(n * G2PITCH + kk + cp2) * 2;
                    bh[nt][0] = *(const uint32_t*)(pBh + ob);
                    bh[nt][1] = *(const uint32_t*)(pBh + ob + 16);
                }
#pragma unroll
                for (int nt = 0; nt < 4; ++nt) {
                    mma16816(acc[0][nh * 4 + nt], ah[0], bh[nt]);
                    mma16816(acc[1][nh * 4 + nt], ah[1], bh[nt]);
                }
                if (use_al) {
#pragma unroll
                    for (int nt = 0; nt < 4; ++nt) {
                        mma16816(acc[0][nh * 4 + nt], al[0], bh[nt]);
                        mma16816(acc[1][nh * 4 + nt], al[1], bh[nt]);
                    }
                }
            }
        }
    }

    // Epilogue
#pragma unroll
    for (int mt = 0; mt < 2; ++mt) {
        const int row0 = gm0 + wm * 32 + mt * 16 + r;
#pragma unroll
        for (int nt = 0; nt < 8; ++nt) {
            const int col = gn0 + wn * 64 + nt * 8 + cp2;
            const float b0 = bias[col], b1 = bias[col + 1];
            float v0 = acc[mt][nt][0] + b0, v1 = acc[mt][nt][1] + b1;
            float v2 = acc[mt][nt][2] + b0, v3 = acc[mt][nt][3] + b1;
            if (Cf32) {
                float2 w0, w1;
                w0.x = v0; w0.y = v1; w1.x = v2; w1.y = v3;
                *(float2*)(Cf32 + (size_t)row0 * Dd + col)       = w0;
                *(float2*)(Cf32 + (size_t)(row0 + 8) * Dd + col) = w1;
            } else {
                __half2 h01 = __floats2half2_rn(v0, v1);
                __half2 h23 = __floats2half2_rn(v2, v3);
                *(uint32_t*)(Oh + (size_t)row0 * Dd + col)       = h2_bits(h01);
                *(uint32_t*)(Oh + (size_t)(row0 + 8) * Dd + col) = h2_bits(h23);
            }
        }
    }
}

// ---------------------------------------------------------------------------
// Flash attention, fp16 mma.sync.
// S = (Qh+Ql) @ K (2 MMAs); PV = Ph @ Vh (1 MMA, l exact fp32);
// exp/pack interleaved with PV MMA (R15).
// R16: ctx output single-rounded fp16 (no lo-half) — feeds 1-pass O-proj.
// Grid (T/128, H, B), 256 threads = 8 warps; warp w owns q rows [16w,16w+16).
// Q pre-scaled by 1/8 in the Q projection epilogue.
// ---------------------------------------------------------------------------
#define QPITCH 72     // fp16; pitch%64==8 -> conflict-free frag loads
#define VPITCH 136
#define AT_QH   0
#define AT_QL   18432
#define AT_K0   36864          // + s*18432 (K hi only)
#define AT_VH   73728
#define AT_BIAS 91136
#define AT_SMEM 91648

__global__ __launch_bounds__(256, 1) void attn_mma_kernel(
    const __half* __restrict__ qh, const __half* __restrict__ ql,
    const __half* __restrict__ kh,
    const __half* __restrict__ vh,
    const int* __restrict__ mask,
    __half* __restrict__ och)
{
    extern __shared__ __align__(128) uint8_t sm[];
    const uint32_t sb = smem_to_u32(sm);
    const int tid = threadIdx.x, wid = tid >> 5, lane = tid & 31;
    const int r = lane >> 2, c2 = (lane & 3) * 2;
    const int b = blockIdx.z, h = blockIdx.y;
    const int q0 = blockIdx.x * 128;
    const size_t gq = ((size_t)(b * Tt + q0)) * Dd + h * HDh;
    const size_t gk = ((size_t)(b * Tt)) * Dd + h * HDh;
    const int* mb = mask + b * Tt;

    // ---- preamble: stage Q (hi/lo) and K tile 0 via cp.async
#pragma unroll
    for (int j = 0; j < 4; ++j) {
        const int i = tid + j * 256, row = i >> 3, seg = i & 7;
        const uint32_t so = (uint32_t)((row * QPITCH + seg * 8) * 2);
        const size_t go = (size_t)row * Dd + seg * 8;
        cp_async16(sb + AT_QH + so, qh + gq + go);
        cp_async16(sb + AT_QL + so, ql + gq + go);
        cp_async16(sb + AT_K0 + so, kh + gk + go);
    }
    cp_commit();

    // ---- V register prefetch: thread -> kv rows 2vj,2vj+1, hd quarter vq*16
    const int vj = tid >> 2;
    const int vq = tid & 3;
    uint4 vr_h[2][2];
#pragma unroll
    for (int rr = 0; rr < 2; ++rr) {
        const size_t g = ((size_t)(b * Tt + 2 * vj + rr)) * Dd + h * HDh + vq * 16;
        vr_h[rr][0] = *(const uint4*)(vh + g);
        vr_h[rr][1] = *(const uint4*)(vh + g + 8);
    }

    float cacc[8][4];
#pragma unroll
    for (int nt = 0; nt < 8; ++nt)
#pragma unroll
        for (int q = 0; q < 4; ++q) cacc[nt][q] = 0.f;
    float m0 = -1e30f, m1 = -1e30f, l0 = 0.f, l1 = 0.f;
    uint32_t qAh[4][4], qAl[4][4];

    for (int c = 0; c < 16; ++c) {
        const int kv0 = c * 128;
        const int s = c & 1;
        cp_wait<0>();
        __syncthreads();   // K(c) visible; prev iter's Vt/K reads done

        // stage V^T(c) from regs (packed pairs via prmt) + mask bias
#pragma unroll
        for (int w = 0; w < 8; ++w) {
            const uint32_t a0 = ((const uint32_t*)&vr_h[0])[w];
            const uint32_t a1 = ((const uint32_t*)&vr_h[1])[w];
            const int hd = vq * 16 + 2 * w;
            *(uint32_t*)(sm + AT_VH + ((hd)     * VPITCH + 2 * vj) * 2) = __byte_perm(a0, a1, 0x5410);
            *(uint32_t*)(sm + AT_VH + ((hd + 1) * VPITCH + 2 * vj) * 2) = __byte_perm(a0, a1, 0x7632);
        }
        if (tid < 128)
            ((float*)(sm + AT_BIAS))[tid] = (mb[kv0 + tid] == 0) ? -1e30f : 0.f;

        // prefetch V(c+1) into regs
        if (c + 1 < 16) {
#pragma unroll
            for (int rr = 0; rr < 2; ++rr) {
                const size_t g = ((size_t)(b * Tt + kv0 + 128 + 2 * vj + rr)) * Dd + h * HDh + vq * 16;
                vr_h[rr][0] = *(const uint4*)(vh + g);
                vr_h[rr][1] = *(const uint4*)(vh + g + 8);
            }
        }

        if (c == 0) {   // Q A-frags, hoisted
#pragma unroll
            for (int kt = 0; kt < 4; ++kt) {
                const uint32_t o  = (uint32_t)(((wid * 16 + r) * QPITCH + kt * 16 + c2) * 2);
                const uint32_t o8 = o + 8 * QPITCH * 2;
                qAh[kt][0] = *(const uint32_t*)(sm + AT_QH + o);
                qAh[kt][1] = *(const uint32_t*)(sm + AT_QH + o8);
                qAh[kt][2] = *(const uint32_t*)(sm + AT_QH + o + 16);
                qAh[kt][3] = *(const uint32_t*)(sm + AT_QH + o8 + 16);
                qAl[kt][0] = *(const uint32_t*)(sm + AT_QL + o);
                qAl[kt][1] = *(const uint32_t*)(sm + AT_QL + o8);
                qAl[kt][2] = *(const uint32_t*)(sm + AT_QL + o + 16);
                qAl[kt][3] = *(const uint32_t*)(sm + AT_QL + o8 + 16);
            }
        }

        // prefetch K(c+1) -> stage s^1 (safe: all warps past sync above)
        if (c + 1 < 16) {
#pragma unroll
            for (int j = 0; j < 4; ++j) {
                const int i = tid + j * 256, row = i >> 3, seg = i & 7;
                const uint32_t so = (uint32_t)((row * QPITCH + seg * 8) * 2);
                const size_t g = gk + (size_t)(kv0 + 128 + row) * Dd + seg * 8;
                cp_async16(sb + AT_K0 + (s ^ 1) * 18432 + so, kh + g);
            }
        }
        cp_commit();
        __syncthreads();   // Vt(c), bias visible

        // ---- S = (Qh+Ql) K^T  (pass-ordered, distance-8 acc reuse)
        const uint8_t* Ksh = sm + AT_K0 + s * 18432;
        float sacc[16][4];
#pragma unroll
        for (int nt = 0; nt < 16; ++nt)
#pragma unroll
            for (int q = 0; q < 4; ++q) sacc[nt][q] = 0.f;
#pragma unroll
        for (int kt = 0; kt < 4; ++kt) {
#pragma unroll
            for (int nh = 0; nh < 2; ++nh) {
                uint32_t bk2[8][2];
#pragma unroll
                for (int nt = 0; nt < 8; ++nt) {
                    const uint32_t o = (uint32_t)((((nh * 8 + nt) * 8 + r) * QPITCH + kt * 16 + c2) * 2);
                    bk2[nt][0] = *(const uint32_t*)(Ksh + o);
                    bk2[nt][1] = *(const uint32_t*)(Ksh + o + 16);
                }
#pragma unroll
                for (int nt = 0; nt < 8; ++nt)
                    mma16816(sacc[nh * 8 + nt], qAh[kt], bk2[nt]);
#pragma unroll
                for (int nt = 0; nt < 8; ++nt)
                    mma16816(sacc[nh * 8 + nt], qAl[kt], bk2[nt]);
            }
        }

        // ---- mask bias + row max (global over the KV tile)
        const float* bias = (const float*)(sm + AT_BIAS);
        float tmax0 = -1e30f, tmax1 = -1e30f;
#pragma unroll
        for (int nt = 0; nt < 16; ++nt) {
            const float2 bv = *(const float2*)(bias + nt * 8 + c2);
            sacc[nt][0] += bv.x; sacc[nt][1] += bv.y;
            sacc[nt][2] += bv.x; sacc[nt][3] += bv.y;
            tmax0 = fmaxf(tmax0, fmaxf(sacc[nt][0], sacc[nt][1]));
            tmax1 = fmaxf(tmax1, fmaxf(sacc[nt][2], sacc[nt][3]));
        }
        tmax0 = fmaxf(tmax0, __shfl_xor_sync(0xffffffffu, tmax0, 1));
        tmax0 = fmaxf(tmax0, __shfl_xor_sync(0xffffffffu, tmax0, 2));
        tmax1 = fmaxf(tmax1, __shfl_xor_sync(0xffffffffu, tmax1, 1));
        tmax1 = fmaxf(tmax1, __shfl_xor_sync(0xffffffffu, tmax1, 2));
        const float mn0 = fmaxf(m0, tmax0), mn1 = fmaxf(m1, tmax1);
        const float al0 = __expf(m0 - mn0), al1 = __expf(m1 - mn1);
        m0 = mn0; m1 = mn1;
#pragma unroll
        for (int nt = 0; nt < 8; ++nt) {
            cacc[nt][0] *= al0; cacc[nt][1] *= al0;
            cacc[nt][2] *= al1; cacc[nt][3] *= al1;
        }

        // ---- interleaved exp/pack + PV MMA per kt (MUFU || tensor)
        float rs0 = 0.f, rs1 = 0.f;
#pragma unroll
        for (int kt = 0; kt < 8; ++kt) {
            uint32_t aPh[4];
#pragma unroll
            for (int u = 0; u < 2; ++u) {
                const int t2 = 2 * kt + u;
                sacc[t2][0] = __expf(sacc[t2][0] - mn0);
                sacc[t2][1] = __expf(sacc[t2][1] - mn0);
                sacc[t2][2] = __expf(sacc[t2][2] - mn1);
                sacc[t2][3] = __expf(sacc[t2][3] - mn1);
                rs0 += sacc[t2][0] + sacc[t2][1];
                rs1 += sacc[t2][2] + sacc[t2][3];
                aPh[2 * u + 0] = h2_bits(__floats2half2_rn(sacc[t2][0], sacc[t2][1]));
                aPh[2 * u + 1] = h2_bits(__floats2half2_rn(sacc[t2][2], sacc[t2][3]));
            }
            uint32_t bv2[8][2];
#pragma unroll
            for (int nt = 0; nt < 8; ++nt) {
                const uint32_t o = (uint32_t)(((nt * 8 + r) * VPITCH + kt * 16 + c2) * 2);
                bv2[nt][0] = *(const uint32_t*)(sm + AT_VH + o);
                bv2[nt][1] = *(const uint32_t*)(sm + AT_VH + o + 16);
            }
#pragma unroll
            for (int nt = 0; nt < 8; ++nt)
                mma16816(cacc[nt], aPh, bv2[nt]);
        }

        // ---- l update (after PV; l not used inside)
        rs0 += __shfl_xor_sync(0xffffffffu, rs0, 1);
        rs0 += __shfl_xor_sync(0xffffffffu, rs0, 2);
        rs1 += __shfl_xor_sync(0xffffffffu, rs1, 1);
        rs1 += __shfl_xor_sync(0xffffffffu, rs1, 2);
        l0 = l0 * al0 + rs0;
        l1 = l1 * al1 + rs1;
    }

    // ---- epilogue: normalize, write ctx as single fp16 (R16)
    const float inv0 = 1.0f / l0, inv1 = 1.0f / l1;
    const int row0 = q0 + wid * 16 + r;
    const size_t ob = ((size_t)(b * Tt) + row0) * Dd + h * HDh;
#pragma unroll
    for (int nt = 0; nt < 8; ++nt) {
        const int col = nt * 8 + c2;
        const float v0 = cacc[nt][0] * inv0, v1 = cacc[nt][1] * inv0;
        const float v2 = cacc[nt][2] * inv1, v3 = cacc[nt][3] * inv1;
        *(uint32_t*)(och + ob + col)          = h2_bits(__floats2half2_rn(v0, v1));
        *(uint32_t*)(och + ob + 8 * Dd + col) = h2_bits(__floats2half2_rn(v2, v3));
    }
}

// ---------------------------------------------------------------------------
extern "C" void kernel_launch(void* const* d_in, const int* in_sizes, int n_in,
                              void* d_out, int out_size)
{
    const float* x  = (const float*)d_in[0];
    const float* Wq = (const float*)d_in[1];
    const float* bq = (const float*)d_in[2];
    const float* Wk = (const float*)d_in[3];
    const float* bk = (const float*)d_in[4];
    const float* Wv = (const float*)d_in[5];
    const float* bv = (const float*)d_in[6];
    const float* Wo = (const float*)d_in[7];
    const float* bo = (const float*)d_in[8];
    const int* mask = (const int*)d_in[9];
    float* out = (float*)d_out;

    __half *xh, *xl, *qhp, *qlp, *khp, *vhp, *chp, *wh, *wl;
    cudaGetSymbolAddress((void**)&xh, g_xh);
    cudaGetSymbolAddress((void**)&xl, g_xl);
    cudaGetSymbolAddress((void**)&qhp, g_qh);
    cudaGetSymbolAddress((void**)&qlp, g_ql);
    cudaGetSymbolAddress((void**)&khp, g_kh);
    cudaGetSymbolAddress((void**)&vhp, g_vh);
    cudaGetSymbolAddress((void**)&chp, g_ch);
    cudaGetSymbolAddress((void**)&wh, g_wh);
    cudaGetSymbolAddress((void**)&wl, g_wl);

    const size_t WSZ = (size_t)Dd * Dd;
    const int n4x = (Mm * Dd) / 4;
    const int n4w = (int)(WSZ / 4);

    // splits
    split_x_kernel<<<(n4x + 255) / 256, 256>>>(x, xh, xl, n4x);
    split_w4_kernel<<<(4 * n4w + 255) / 256, 256>>>(Wq, Wk, Wv, Wo, wh, wl, n4w);

    cudaFuncSetAttribute(gemm3p_bk32,
                         cudaFuncAttributeMaxDynamicSharedMemorySize, GSMEM_B);
    cudaFuncSetAttribute(gemm2p_bk64,
                         cudaFuncAttributeMaxDynamicSharedMemorySize, G2SMEM_B);
    dim3 ggrid(Dd / 128, Mm / 128);

    // Q projection: 3-pass BK32 -> fp16 hi/lo, pre-scaled 1/8
    gemm3p_bk32<<<ggrid, 256, GSMEM_B>>>(xh, xl, wh + 0 * WSZ, wl + 0 * WSZ, bq,
                                         qhp, qlp, 0.125f);
    // K,V projections: 2-pass BK64 -> single fp16
    gemm2p_bk64<<<ggrid, 256, G2SMEM_B>>>(xh, xl, wh + 1 * WSZ, bk, nullptr, khp, 1);
    gemm2p_bk64<<<ggrid, 256, G2SMEM_B>>>(xh, xl, wh + 2 * WSZ, bv, nullptr, vhp, 1);

    // fused attention -> ctx single fp16
    cudaFuncSetAttribute(attn_mma_kernel,
                         cudaFuncAttributeMaxDynamicSharedMemorySize, AT_SMEM);
    attn_mma_kernel<<<dim3(Tt / 128, Hh, Bb), 256, AT_SMEM>>>(
        qhp, qlp, khp, vhp, mask, chp);

    // Output projection: 1-pass BK64 (R16) -> fp32
    gemm2p_bk64<<<ggrid, 256, G2SMEM_B>>>(chp, nullptr, wh + 3 * WSZ, bo, out, nullptr, 0);
}

// round 17
// speedup vs baseline: 1.1116x; 1.0592x over previous
#include <cuda_runtime.h>
#include <cuda_fp16.h>
#include <cstdint>

// Problem constants
#define Bb  4
#define Tt  2048
#define Dd  1024
#define Hh  16
#define HDh 64
#define Mm  (Bb * Tt)   // 8192 rows

// ---------------------------------------------------------------------------
// Scratch (device globals: allocation-free rule). All fp16.
// ---------------------------------------------------------------------------
__device__ __half g_xh[(size_t)Mm * Dd];
__device__ __half g_xl[(size_t)Mm * Dd];
__device__ __half g_qh[(size_t)Mm * Dd];
__device__ __half g_ql[(size_t)Mm * Dd];
__device__ __half g_kh[(size_t)Mm * Dd];          // K single-rounded
__device__ __half g_vh[(size_t)Mm * Dd];          // V single-rounded (R17: 1-pass proj)
__device__ __half g_ch[(size_t)Mm * Dd];          // ctx single-rounded
__device__ __half g_wh[4 * (size_t)Dd * Dd];
__device__ __half g_wl[4 * (size_t)Dd * Dd];

// ---------------------------------------------------------------------------
// sm_100-base helpers: cp.async + mma.sync fp16 (tcgen05 unavailable here)
// ---------------------------------------------------------------------------
__device__ __forceinline__ uint32_t smem_to_u32(const void* p) {
    uint32_t a;
    asm("{ .reg .u64 t; cvta.to.shared.u64 t, %1; cvt.u32.u64 %0, t; }"
        : "=r"(a) : "l"(p));
    return a;
}
__device__ __forceinline__ void cp_async16(uint32_t smem_addr, const void* gptr) {
    asm volatile("cp.async.cg.shared.global [%0], [%1], 16;"
                 :: "r"(smem_addr), "l"(gptr));
}
__device__ __forceinline__ void cp_commit() {
    asm volatile("cp.async.commit_group;");
}
template <int N>
__device__ __forceinline__ void cp_wait() {
    asm volatile("cp.async.wait_group %0;" :: "n"(N));
}
// D += A*B, m16n8k16 fp16 in / fp32 accum; A row-major, B col-major
__device__ __forceinline__ void mma16816(float* d, const uint32_t* a, const uint32_t* b) {
    asm volatile(
        "mma.sync.aligned.m16n8k16.row.col.f32.f16.f16.f32 "
        "{%0,%1,%2,%3}, {%4,%5,%6,%7}, {%8,%9}, {%0,%1,%2,%3};"
        : "+f"(d[0]), "+f"(d[1]), "+f"(d[2]), "+f"(d[3])
        : "r"(a[0]), "r"(a[1]), "r"(a[2]), "r"(a[3]), "r"(b[0]), "r"(b[1]));
}
__device__ __forceinline__ uint32_t h2_bits(__half2 v) {
    union { __half2 h; uint32_t u; } cv; cv.h = v; return cv.u;
}
// hi/lo split of one float into two fp16
__device__ __forceinline__ void split_h(float v, __half& hi, __half& lo) {
    hi = __float2half_rn(v);
    lo = __float2half_rn(v - __half2float(hi));
}

// ---------------------------------------------------------------------------
// Split kernels (fp32 -> fp16 hi/lo)
// ---------------------------------------------------------------------------
__global__ __launch_bounds__(256) void split_x_kernel(
    const float* __restrict__ src,
    __half* __restrict__ hi, __half* __restrict__ lo, int n4)
{
    int i = blockIdx.x * blockDim.x + threadIdx.x;
    if (i >= n4) return;
    float4 v = ((const float4*)src)[i];
    __half h0, h1, h2, h3, l0, l1, l2, l3;
    split_h(v.x, h0, l0); split_h(v.y, h1, l1);
    split_h(v.z, h2, l2); split_h(v.w, h3, l3);
    union { __half b[4]; uint2 u; } ph, pl;
    ph.b[0] = h0; ph.b[1] = h1; ph.b[2] = h2; ph.b[3] = h3;
    pl.b[0] = l0; pl.b[1] = l1; pl.b[2] = l2; pl.b[3] = l3;
    ((uint2*)hi)[i] = ph.u;
    ((uint2*)lo)[i] = pl.u;
}

// all 4 weight matrices in one launch; dest arrays are contiguous per-matrix
__global__ __launch_bounds__(256) void split_w4_kernel(
    const float* __restrict__ w0, const float* __restrict__ w1,
    const float* __restrict__ w2, const float* __restrict__ w3,
    __half* __restrict__ hi, __half* __restrict__ lo, int n4_each)
{
    int i = blockIdx.x * blockDim.x + threadIdx.x;
    if (i >= 4 * n4_each) return;
    const int m = i / n4_each, j = i - m * n4_each;
    const float* src = (m == 0) ? w0 : (m == 1) ? w1 : (m == 2) ? w2 : w3;
    float4 v = ((const float4*)src)[j];
    __half h0, h1, h2, h3, l0, l1, l2, l3;
    split_h(v.x, h0, l0); split_h(v.y, h1, l1);
    split_h(v.z, h2, l2); split_h(v.w, h3, l3);
    union { __half b[4]; uint2 u; } ph, pl;
    ph.b[0] = h0; ph.b[1] = h1; ph.b[2] = h2; ph.b[3] = h3;
    pl.b[0] = l0; pl.b[1] = l1; pl.b[2] = l2; pl.b[3] = l3;
    ((uint2*)hi)[i] = ph.u;
    ((uint2*)lo)[i] = pl.u;
}

// ---------------------------------------------------------------------------
// 3-pass fp16 split GEMM (Q projection): C = (Ah+Al) @ (Bh+Bl)^T + bias,
// dropping Al*Bl. BK=32, double-buffered, single sync per chunk.
// Output: fp16 hi/lo, scaled.
// ---------------------------------------------------------------------------
#define GPITCH 40
#define GTILE_B (128 * GPITCH * 2)
#define GSTAGE_B (4 * GTILE_B)
#define GSMEM_B (2 * GSTAGE_B)

__global__ __launch_bounds__(256, 2) void gemm3p_bk32(
    const __half* __restrict__ Ah, const __half* __restrict__ Al,
    const __half* __restrict__ Bh, const __half* __restrict__ Bl,
    const float* __restrict__ bias,
    __half* __restrict__ Oh, __half* __restrict__ Ol, float scale)
{
    extern __shared__ __align__(128) uint8_t smem[];
    const int tid  = threadIdx.x;
    const int wid  = tid >> 5;
    const int lane = tid & 31;
    const int wm   = wid & 3;
    const int wn   = wid >> 2;
    const int gm0  = blockIdx.y * 128;
    const int gn0  = blockIdx.x * 128;
    const uint32_t sbase = smem_to_u32(smem);

    const __half* srcs[4] = { Ah, Al, Bh, Bl };

    auto issue = [&](int s, int c) {
        const int k0 = c * 32;
#pragma unroll
        for (int t = 0; t < 4; ++t) {
            const __half* src = srcs[t];
            const int rbase = (t < 2) ? gm0 : gn0;
#pragma unroll
            for (int j = 0; j < 2; ++j) {
                const int i = tid + j * 256;
                const int row = i >> 2, chunk = i & 3;
                const uint32_t sa = sbase + s * GSTAGE_B + t * GTILE_B
                                  + (uint32_t)(row * GPITCH + chunk * 8) * 2;
                const void* g = src + (size_t)(rbase + row) * Dd + k0 + chunk * 8;
                cp_async16(sa, g);
            }
        }
        cp_commit();
    };

    float acc[2][8][4];
#pragma unroll
    for (int mt = 0; mt < 2; ++mt)
#pragma unroll
        for (int nt = 0; nt < 8; ++nt)
#pragma unroll
            for (int q = 0; q < 4; ++q) acc[mt][nt][q] = 0.f;

    const int r   = lane >> 2;
    const int cp2 = (lane & 3) * 2;

    issue(0, 0);

    for (int c = 0; c < 32; ++c) {
        const int s = c & 1;
        cp_wait<0>();
        __syncthreads();
        if (c + 1 < 32) issue(s ^ 1, c + 1);

        const uint8_t* stg = smem + s * GSTAGE_B;
        const uint8_t* pAh = stg;
        const uint8_t* pAl = stg + GTILE_B;
        const uint8_t* pBh = stg + 2 * GTILE_B;
        const uint8_t* pBl = stg + 3 * GTILE_B;

#pragma unroll
        for (int ks = 0; ks < 2; ++ks) {
            const int kk = ks * 16;
            uint32_t ah[2][4], al[2][4];
#pragma unroll
            for (int mt = 0; mt < 2; ++mt) {
                const int row = wm * 32 + mt * 16 + r;
                const uint32_t o00 = (uint32_t)(row * GPITCH + kk + cp2) * 2;
                const uint32_t o10 = (uint32_t)((row + 8) * GPITCH + kk + cp2) * 2;
                ah[mt][0] = *(const uint32_t*)(pAh + o00);
                ah[mt][1] = *(const uint32_t*)(pAh + o10);
                ah[mt][2] = *(const uint32_t*)(pAh + o00 + 16);
                ah[mt][3] = *(const uint32_t*)(pAh + o10 + 16);
                al[mt][0] = *(const uint32_t*)(pAl + o00);
                al[mt][1] = *(const uint32_t*)(pAl + o10);
                al[mt][2] = *(const uint32_t*)(pAl + o00 + 16);
                al[mt][3] = *(const uint32_t*)(pAl + o10 + 16);
            }
#pragma unroll
            for (int nh = 0; nh < 2; ++nh) {
                uint32_t bh[4][2], bl[4][2];
#pragma unroll
                for (int nt = 0; nt < 4; ++nt) {
                    const int n = wn * 64 + (nh * 4 + nt) * 8 + r;
                    const uint32_t ob = (uint32_t)(n * GPITCH + kk + cp2) * 2;
                    bh[nt][0] = *(const uint32_t*)(pBh + ob);
                    bh[nt][1] = *(const uint32_t*)(pBh + ob + 16);
                    bl[nt][0] = *(const uint32_t*)(pBl + ob);
                    bl[nt][1] = *(const uint32_t*)(pBl + ob + 16);
                }
#pragma unroll
                for (int nt = 0; nt < 4; ++nt) {
                    mma16816(acc[0][nh * 4 + nt], ah[0], bh[nt]);
                    mma16816(acc[1][nh * 4 + nt], ah[1], bh[nt]);
                }
#pragma unroll
                for (int nt = 0; nt < 4; ++nt) {
                    mma16816(acc[0][nh * 4 + nt], al[0], bh[nt]);
                    mma16816(acc[1][nh * 4 + nt], al[1], bh[nt]);
                }
#pragma unroll
                for (int nt = 0; nt < 4; ++nt) {
                    mma16816(acc[0][nh * 4 + nt], ah[0], bl[nt]);
                    mma16816(acc[1][nh * 4 + nt], ah[1], bl[nt]);
                }
            }
        }
    }

    // Epilogue: scaled fp16 hi/lo
#pragma unroll
    for (int mt = 0; mt < 2; ++mt) {
        const int row0 = gm0 + wm * 32 + mt * 16 + r;
#pragma unroll
        for (int nt = 0; nt < 8; ++nt) {
            const int col = gn0 + wn * 64 + nt * 8 + cp2;
            const float b0 = bias[col], b1 = bias[col + 1];
            float v0 = (acc[mt][nt][0] + b0) * scale, v1 = (acc[mt][nt][1] + b1) * scale;
            float v2 = (acc[mt][nt][2] + b0) * scale, v3 = (acc[mt][nt][3] + b1) * scale;
            __half2 h01 = __floats2half2_rn(v0, v1);
            __half2 h23 = __floats2half2_rn(v2, v3);
            __half2 l01 = __floats2half2_rn(
                v0 - __half2float(__low2half(h01)), v1 - __half2float(__high2half(h01)));
            __half2 l23 = __floats2half2_rn(
                v2 - __half2float(__low2half(h23)), v3 - __half2float(__high2half(h23)));
            *(uint32_t*)(Oh + (size_t)row0 * Dd + col)       = h2_bits(h01);
            *(uint32_t*)(Ol + (size_t)row0 * Dd + col)       = h2_bits(l01);
            *(uint32_t*)(Oh + (size_t)(row0 + 8) * Dd + col) = h2_bits(h23);
            *(uint32_t*)(Ol + (size_t)(row0 + 8) * Dd + col) = h2_bits(l23);
        }
    }
}

// ---------------------------------------------------------------------------
// 1/2-pass fp16 split GEMM (K/V/O projections): C = (Ah[+Al]) @ Bh^T + bias.
// BK=64, double-buffered, single sync per chunk. use_al selects 2-pass.
// Output: fp16 single (Oh) or fp32 (Cf32).
// ---------------------------------------------------------------------------
#define G2PITCH 72
#define G2TILE_B (128 * G2PITCH * 2)      // 18432
#define G2STAGE_B (3 * G2TILE_B)          // 55296
#define G2SMEM_B (2 * G2STAGE_B)          // 110592

__global__ __launch_bounds__(256, 2) void gemm2p_bk64(
    const __half* __restrict__ Ah, const __half* __restrict__ Al,
    const __half* __restrict__ Bh,
    const float* __restrict__ bias,
    float* __restrict__ Cf32, __half* __restrict__ Oh, int use_al)
{
    extern __shared__ __align__(128) uint8_t smem[];
    const int tid  = threadIdx.x;
    const int wid  = tid >> 5;
    const int lane = tid & 31;
    const int wm   = wid & 3;
    const int wn   = wid >> 2;
    const int gm0  = blockIdx.y * 128;
    const int gn0  = blockIdx.x * 128;
    const uint32_t sbase = smem_to_u32(smem);

    const __half* srcs[3] = { Ah, Al, Bh };

    auto issue = [&](int s, int c) {
        const int k0 = c * 64;
#pragma unroll
        for (int t = 0; t < 3; ++t) {
            if (t == 1 && !use_al) continue;
            const __half* src = srcs[t];
            const int rbase = (t < 2) ? gm0 : gn0;
#pragma unroll
            for (int j = 0; j < 4; ++j) {
                const int i = tid + j * 256;
                const int row = i >> 3, seg = i & 7;
                const uint32_t sa = sbase + s * G2STAGE_B + t * G2TILE_B
                                  + (uint32_t)(row * G2PITCH + seg * 8) * 2;
                const void* g = src + (size_t)(rbase + row) * Dd + k0 + seg * 8;
                cp_async16(sa, g);
            }
        }
        cp_commit();
    };

    float acc[2][8][4];
#pragma unroll
    for (int mt = 0; mt < 2; ++mt)
#pragma unroll
        for (int nt = 0; nt < 8; ++nt)
#pragma unroll
            for (int q = 0; q < 4; ++q) acc[mt][nt][q] = 0.f;

    const int r   = lane >> 2;
    const int cp2 = (lane & 3) * 2;

    issue(0, 0);

    for (int c = 0; c < 16; ++c) {
        const int s = c & 1;
        cp_wait<0>();
        __syncthreads();
        if (c + 1 < 16) issue(s ^ 1, c + 1);

        const uint8_t* stg = smem + s * G2STAGE_B;
        const uint8_t* pAh = stg;
        const uint8_t* pAl = stg + G2TILE_B;
        const uint8_t* pBh = stg + 2 * G2TILE_B;

#pragma unroll
        for (int ks = 0; ks < 4; ++ks) {
            const int kk = ks * 16;
            uint32_t ah[2][4], al[2][4];
#pragma unroll
            for (int mt = 0; mt < 2; ++mt) {
                const int row = wm * 32 + mt * 16 + r;
                const uint32_t o00 = (uint32_t)(row * G2PITCH + kk + cp2) * 2;
                const uint32_t o10 = (uint32_t)((row + 8) * G2PITCH + kk + cp2) * 2;
                ah[mt][0] = *(const uint32_t*)(pAh + o00);
                ah[mt][1] = *(const uint32_t*)(pAh + o10);
                ah[mt][2] = *(const uint32_t*)(pAh + o00 + 16);
                ah[mt][3] = *(const uint32_t*)(pAh + o10 + 16);
                if (use_al) {
                    al[mt][0] = *(const uint32_t*)(pAl + o00);
                    al[mt][1] = *(const uint32_t*)(pAl + o10);
                    al[mt][2] = *(const uint32_t*)(pAl + o00 + 16);
                    al[mt][3] = *(const uint32_t*)(pAl + o10 + 16);
                }
            }
#pragma unroll
            for (int nh = 0; nh < 2; ++nh) {
                uint32_t bh[4][2];
#pragma unroll
                for (int nt = 0; nt < 4; ++nt) {
                    const int n = wn * 64 + (nh * 4 + nt) * 8 + r;
                    const uint32_t ob = (uint32_t)(n * G2PITCH + kk + cp2) * 2;
                    bh[nt][0] = *(const uint32_t*)(pBh + ob);
                    bh[nt][1] = *(const uint32_t*)(pBh + ob + 16);
                }
#pragma unroll
                for (int nt = 0; nt < 4; ++nt) {
                    mma16816(acc[0][nh * 4 + nt], ah[0], bh[nt]);
                    mma16816(acc[1][nh * 4 + nt], ah[1], bh[nt]);
                }
                if (use_al) {
#pragma unroll
                    for (int nt = 0; nt < 4; ++nt) {
                        mma16816(acc[0][nh * 4 + nt], al[0], bh[nt]);
                        mma16816(acc[1][nh * 4 + nt], al[1], bh[nt]);
                    }
                }
            }
        }
    }

    // Epilogue
#pragma unroll
    for (int mt = 0; mt < 2; ++mt) {
        const int row0 = gm0 + wm * 32 + mt * 16 + r;
#pragma unroll
        for (int nt = 0; nt < 8; ++nt) {
            const int col = gn0 + wn * 64 + nt * 8 + cp2;
            const float b0 = bias[col], b1 = bias[col + 1];
            float v0 = acc[mt][nt][0] + b0, v1 = acc[mt][nt][1] + b1;
            float v2 = acc[mt][nt][2] + b0, v3 = acc[mt][nt][3] + b1;
            if (Cf32) {
                float2 w0, w1;
                w0.x = v0; w0.y = v1; w1.x = v2; w1.y = v3;
                *(float2*)(Cf32 + (size_t)row0 * Dd + col)       = w0;
                *(float2*)(Cf32 + (size_t)(row0 + 8) * Dd + col) = w1;
            } else {
                __half2 h01 = __floats2half2_rn(v0, v1);
                __half2 h23 = __floats2half2_rn(v2, v3);
                *(uint32_t*)(Oh + (size_t)row0 * Dd + col)       = h2_bits(h01);
                *(uint32_t*)(Oh + (size_t)(row0 + 8) * Dd + col) = h2_bits(h23);
            }
        }
    }
}

// ---------------------------------------------------------------------------
// Flash attention, fp16 mma.sync.
// S = (Qh+Ql) @ K (2 MMAs); PV = Ph @ Vh (1 MMA, l exact fp32);
// exp/pack interleaved with PV MMA. ctx output single-rounded fp16.
// Grid (T/128, H, B), 256 threads = 8 warps; warp w owns q rows [16w,16w+16).
// Q pre-scaled by 1/8 in the Q projection epilogue.
// ---------------------------------------------------------------------------
#define QPITCH 72     // fp16; pitch%64==8 -> conflict-free frag loads
#define VPITCH 136
#define AT_QH   0
#define AT_QL   18432
#define AT_K0   36864          // + s*18432 (K hi only)
#define AT_VH   73728
#define AT_BIAS 91136
#define AT_SMEM 91648

__global__ __launch_bounds__(256, 1) void attn_mma_kernel(
    const __half* __restrict__ qh, const __half* __restrict__ ql,
    const __half* __restrict__ kh,
    const __half* __restrict__ vh,
    const int* __restrict__ mask,
    __half* __restrict__ och)
{
    extern __shared__ __align__(128) uint8_t sm[];
    const uint32_t sb = smem_to_u32(sm);
    const int tid = threadIdx.x, wid = tid >> 5, lane = tid & 31;
    const int r = lane >> 2, c2 = (lane & 3) * 2;
    const int b = blockIdx.z, h = blockIdx.y;
    const int q0 = blockIdx.x * 128;
    const size_t gq = ((size_t)(b * Tt + q0)) * Dd + h * HDh;
    const size_t gk = ((size_t)(b * Tt)) * Dd + h * HDh;
    const int* mb = mask + b * Tt;

    // ---- preamble: stage Q (hi/lo) and K tile 0 via cp.async
#pragma unroll
    for (int j = 0; j < 4; ++j) {
        const int i = tid + j * 256, row = i >> 3, seg = i & 7;
        const uint32_t so = (uint32_t)((row * QPITCH + seg * 8) * 2);
        const size_t go = (size_t)row * Dd + seg * 8;
        cp_async16(sb + AT_QH + so, qh + gq + go);
        cp_async16(sb + AT_QL + so, ql + gq + go);
        cp_async16(sb + AT_K0 + so, kh + gk + go);
    }
    cp_commit();

    // ---- V register prefetch: thread -> kv rows 2vj,2vj+1, hd quarter vq*16
    const int vj = tid >> 2;
    const int vq = tid & 3;
    uint4 vr_h[2][2];
#pragma unroll
    for (int rr = 0; rr < 2; ++rr) {
        const size_t g = ((size_t)(b * Tt + 2 * vj + rr)) * Dd + h * HDh + vq * 16;
        vr_h[rr][0] = *(const uint4*)(vh + g);
        vr_h[rr][1] = *(const uint4*)(vh + g + 8);
    }

    float cacc[8][4];
#pragma unroll
    for (int nt = 0; nt < 8; ++nt)
#pragma unroll
        for (int q = 0; q < 4; ++q) cacc[nt][q] = 0.f;
    float m0 = -1e30f, m1 = -1e30f, l0 = 0.f, l1 = 0.f;
    uint32_t qAh[4][4], qAl[4][4];

    for (int c = 0; c < 16; ++c) {
        const int kv0 = c * 128;
        const int s = c & 1;
        cp_wait<0>();
        __syncthreads();   // K(c) visible; prev iter's Vt/K reads done

        // stage V^T(c) from regs (packed pairs via prmt) + mask bias
#pragma unroll
        for (int w = 0; w < 8; ++w) {
            const uint32_t a0 = ((const uint32_t*)&vr_h[0])[w];
            const uint32_t a1 = ((const uint32_t*)&vr_h[1])[w];
            const int hd = vq * 16 + 2 * w;
            *(uint32_t*)(sm + AT_VH + ((hd)     * VPITCH + 2 * vj) * 2) = __byte_perm(a0, a1, 0x5410);
            *(uint32_t*)(sm + AT_VH + ((hd + 1) * VPITCH + 2 * vj) * 2) = __byte_perm(a0, a1, 0x7632);
        }
        if (tid < 128)
            ((float*)(sm + AT_BIAS))[tid] = (mb[kv0 + tid] == 0) ? -1e30f : 0.f;

        // prefetch V(c+1) into regs
        if (c + 1 < 16) {
#pragma unroll
            for (int rr = 0; rr < 2; ++rr) {
                const size_t g = ((size_t)(b * Tt + kv0 + 128 + 2 * vj + rr)) * Dd + h * HDh + vq * 16;
                vr_h[rr][0] = *(const uint4*)(vh + g);
                vr_h[rr][1] = *(const uint4*)(vh + g + 8);
            }
        }

        if (c == 0) {   // Q A-frags, hoisted
#pragma unroll
            for (int kt = 0; kt < 4; ++kt) {
                const uint32_t o  = (uint32_t)(((wid * 16 + r) * QPITCH + kt * 16 + c2) * 2);
                const uint32_t o8 = o + 8 * QPITCH * 2;
                qAh[kt][0] = *(const uint32_t*)(sm + AT_QH + o);
                qAh[kt][1] = *(const uint32_t*)(sm + AT_QH + o8);
                qAh[kt][2] = *(const uint32_t*)(sm + AT_QH + o + 16);
                qAh[kt][3] = *(const uint32_t*)(sm + AT_QH + o8 + 16);
                qAl[kt][0] = *(const uint32_t*)(sm + AT_QL + o);
                qAl[kt][1] = *(const uint32_t*)(sm + AT_QL + o8);
                qAl[kt][2] = *(const uint32_t*)(sm + AT_QL + o + 16);
                qAl[kt][3] = *(const uint32_t*)(sm + AT_QL + o8 + 16);
            }
        }

        // prefetch K(c+1) -> stage s^1 (safe: all warps past sync above)
        if (c + 1 < 16) {
#pragma unroll
            for (int j = 0; j < 4; ++j) {
                const int i = tid + j * 256, row = i >> 3, seg = i & 7;
                const uint32_t so = (uint32_t)((row * QPITCH + seg * 8) * 2);
                const size_t g = gk + (size_t)(kv0 + 128 + row) * Dd + seg * 8;
                cp_async16(sb + AT_K0 + (s ^ 1) * 18432 + so, kh + g);
            }
        }
        cp_commit();
        __syncthreads();   // Vt(c), bias visible

        // ---- S = (Qh+Ql) K^T  (pass-ordered, distance-8 acc reuse)
        const uint8_t* Ksh = sm + AT_K0 + s * 18432;
        float sacc[16][4];
#pragma unroll
        for (int nt = 0; nt < 16; ++nt)
#pragma unroll
            for (int q = 0; q < 4; ++q) sacc[nt][q] = 0.f;
#pragma unroll
        for (int kt = 0; kt < 4; ++kt) {
#pragma unroll
            for (int nh = 0; nh < 2; ++nh) {
                uint32_t bk2[8][2];
#pragma unroll
                for (int nt = 0; nt < 8; ++nt) {
                    const uint32_t o = (uint32_t)((((nh * 8 + nt) * 8 + r) * QPITCH + kt * 16 + c2) * 2);
                    bk2[nt][0] = *(const uint32_t*)(Ksh + o);
                    bk2[nt][1] = *(const uint32_t*)(Ksh + o + 16);
                }
#pragma unroll
                for (int nt = 0; nt < 8; ++nt)
                    mma16816(sacc[nh * 8 + nt], qAh[kt], bk2[nt]);
#pragma unroll
                for (int nt = 0; nt < 8; ++nt)
                    mma16816(sacc[nh * 8 + nt], qAl[kt], bk2[nt]);
            }
        }

        // ---- mask bias + row max (global over the KV tile)
        const float* bias = (const float*)(sm + AT_BIAS);
        float tmax0 = -1e30f, tmax1 = -1e30f;
#pragma unroll
        for (int nt = 0; nt < 16; ++nt) {
            const float2 bv = *(const float2*)(bias + nt * 8 + c2);
            sacc[nt][0] += bv.x; sacc[nt][1] += bv.y;
            sacc[nt][2] += bv.x; sacc[nt][3] += bv.y;
            tmax0 = fmaxf(tmax0, fmaxf(sacc[nt][0], sacc[nt][1]));
            tmax1 = fmaxf(tmax1, fmaxf(sacc[nt][2], sacc[nt][3]));
        }
        tmax0 = fmaxf(tmax0, __shfl_xor_sync(0xffffffffu, tmax0, 1));
        tmax0 = fmaxf(tmax0, __shfl_xor_sync(0xffffffffu, tmax0, 2));
        tmax1 = fmaxf(tmax1, __shfl_xor_sync(0xffffffffu, tmax1, 1));
        tmax1 = fmaxf(tmax1, __shfl_xor_sync(0xffffffffu, tmax1, 2));
        const float mn0 = fmaxf(m0, tmax0), mn1 = fmaxf(m1, tmax1);
        const float al0 = __expf(m0 - mn0), al1 = __expf(m1 - mn1);
        m0 = mn0; m1 = mn1;
#pragma unroll
        for (int nt = 0; nt < 8; ++nt) {
            cacc[nt][0] *= al0; cacc[nt][1] *= al0;
            cacc[nt][2] *= al1; cacc[nt][3] *= al1;
        }

        // ---- interleaved exp/pack + PV MMA per kt (MUFU || tensor)
        float rs0 = 0.f, rs1 = 0.f;
#pragma unroll
        for (int kt = 0; kt < 8; ++kt) {
            uint32_t aPh[4];
#pragma unroll
            for (int u = 0; u < 2; ++u) {
                const int t2 = 2 * kt + u;
                sacc[t2][0] = __expf(sacc[t2][0] - mn0);
                sacc[t2][1] = __expf(sacc[t2][1] - mn0);
                sacc[t2][2] = __expf(sacc[t2][2] - mn1);
                sacc[t2][3] = __expf(sacc[t2][3] - mn1);
                rs0 += sacc[t2][0] + sacc[t2][1];
                rs1 += sacc[t2][2] + sacc[t2][3];
                aPh[2 * u + 0] = h2_bits(__floats2half2_rn(sacc[t2][0], sacc[t2][1]));
                aPh[2 * u + 1] = h2_bits(__floats2half2_rn(sacc[t2][2], sacc[t2][3]));
            }
            uint32_t bv2[8][2];
#pragma unroll
            for (int nt = 0; nt < 8; ++nt) {
                const uint32_t o = (uint32_t)(((nt * 8 + r) * VPITCH + kt * 16 + c2) * 2);
                bv2[nt][0] = *(const uint32_t*)(sm + AT_VH + o);
                bv2[nt][1] = *(const uint32_t*)(sm + AT_VH + o + 16);
            }
#pragma unroll
            for (int nt = 0; nt < 8; ++nt)
                mma16816(cacc[nt], aPh, bv2[nt]);
        }

        // ---- l update (after PV; l not used inside)
        rs0 += __shfl_xor_sync(0xffffffffu, rs0, 1);
        rs0 += __shfl_xor_sync(0xffffffffu, rs0, 2);
        rs1 += __shfl_xor_sync(0xffffffffu, rs1, 1);
        rs1 += __shfl_xor_sync(0xffffffffu, rs1, 2);
        l0 = l0 * al0 + rs0;
        l1 = l1 * al1 + rs1;
    }

    // ---- epilogue: normalize, write ctx as single fp16
    const float inv0 = 1.0f / l0, inv1 = 1.0f / l1;
    const int row0 = q0 + wid * 16 + r;
    const size_t ob = ((size_t)(b * Tt) + row0) * Dd + h * HDh;
#pragma unroll
    for (int nt = 0; nt < 8; ++nt) {
        const int col = nt * 8 + c2;
        const float v0 = cacc[nt][0] * inv0, v1 = cacc[nt][1] * inv0;
        const float v2 = cacc[nt][2] * inv1, v3 = cacc[nt][3] * inv1;
        *(uint32_t*)(och + ob + col)          = h2_bits(__floats2half2_rn(v0, v1));
        *(uint32_t*)(och + ob + 8 * Dd + col) = h2_bits(__floats2half2_rn(v2, v3));
    }
}

// ---------------------------------------------------------------------------
extern "C" void kernel_launch(void* const* d_in, const int* in_sizes, int n_in,
                              void* d_out, int out_size)
{
    const float* x  = (const float*)d_in[0];
    const float* Wq = (const float*)d_in[1];
    const float* bq = (const float*)d_in[2];
    const float* Wk = (const float*)d_in[3];
    const float* bk = (const float*)d_in[4];
    const float* Wv = (const float*)d_in[5];
    const float* bv = (const float*)d_in[6];
    const float* Wo = (const float*)d_in[7];
    const float* bo = (const float*)d_in[8];
    const int* mask = (const int*)d_in[9];
    float* out = (float*)d_out;

    __half *xh, *xl, *qhp, *qlp, *khp, *vhp, *chp, *wh, *wl;
    cudaGetSymbolAddress((void**)&xh, g_xh);
    cudaGetSymbolAddress((void**)&xl, g_xl);
    cudaGetSymbolAddress((void**)&qhp, g_qh);
    cudaGetSymbolAddress((void**)&qlp, g_ql);
    cudaGetSymbolAddress((void**)&khp, g_kh);
    cudaGetSymbolAddress((void**)&vhp, g_vh);
    cudaGetSymbolAddress((void**)&chp, g_ch);
    cudaGetSymbolAddress((void**)&wh, g_wh);
    cudaGetSymbolAddress((void**)&wl, g_wl);

    const size_t WSZ = (size_t)Dd * Dd;
    const int n4x = (Mm * Dd) / 4;
    const int n4w = (int)(WSZ / 4);

    // splits
    split_x_kernel<<<(n4x + 255) / 256, 256>>>(x, xh, xl, n4x);
    split_w4_kernel<<<(4 * n4w + 255) / 256, 256>>>(Wq, Wk, Wv, Wo, wh, wl, n4w);

    cudaFuncSetAttribute(gemm3p_bk32,
                         cudaFuncAttributeMaxDynamicSharedMemorySize, GSMEM_B);
    cudaFuncSetAttribute(gemm2p_bk64,
                         cudaFuncAttributeMaxDynamicSharedMemorySize, G2SMEM_B);
    dim3 ggrid(Dd / 128, Mm / 128);

    // Q projection: 3-pass BK32 -> fp16 hi/lo, pre-scaled 1/8
    gemm3p_bk32<<<ggrid, 256, GSMEM_B>>>(xh, xl, wh + 0 * WSZ, wl + 0 * WSZ, bq,
                                         qhp, qlp, 0.125f);
    // K projection: 2-pass BK64 -> single fp16
    gemm2p_bk64<<<ggrid, 256, G2SMEM_B>>>(xh, xl, wh + 1 * WSZ, bk, nullptr, khp, 1);
    // V projection: 1-pass BK64 (R17) -> single fp16
    gemm2p_bk64<<<ggrid, 256, G2SMEM_B>>>(xh, nullptr, wh + 2 * WSZ, bv, nullptr, vhp, 0);

    // fused attention -> ctx single fp16
    cudaFuncSetAttribute(attn_mma_kernel,
                         cudaFuncAttributeMaxDynamicSharedMemorySize, AT_SMEM);
    attn_mma_kernel<<<dim3(Tt / 128, Hh, Bb), 256, AT_SMEM>>>(
        qhp, qlp, khp, vhp, mask, chp);

    // Output projection: 1-pass BK64 -> fp32
    gemm2p_bk64<<<ggrid, 256, G2SMEM_B>>>(chp, nullptr, wh + 3 * WSZ, bo, out, nullptr, 0);
}